// round 11
// baseline (speedup 1.0000x reference)
#include <cuda_runtime.h>
#include <cuda_fp16.h>
#include <math.h>
#include <stdint.h>

#define BATCH 16
#define CHN   640
#define SP    4096
#define TT    77
#define XDIM  768
#define NHE   8
#define HDIM  80
#define INNER 640

// ---------------- scratch ----------------
__device__ float  g_q   [(size_t)BATCH * SP * INNER];   // fp32 (attn input)
__device__ float  g_k   [(size_t)BATCH * TT * INNER];
__device__ float  g_v   [(size_t)BATCH * TT * INNER];
__device__ __half g_at16[(size_t)BATCH * SP * INNER];   // attn out
__device__ __half g_e16 [(size_t)BATCH * TT * XDIM];
__device__ __half g_wq16[(size_t)INNER * CHN];          // [N][K]
__device__ __half g_wk16[(size_t)INNER * XDIM];
__device__ __half g_wv16[(size_t)INNER * XDIM];
__device__ __half g_wo16[(size_t)CHN * INNER];
__device__ float  g_mu  [(size_t)BATCH * SP];
__device__ float  g_rs  [(size_t)BATCH * SP];

// ---------------- helpers ----------------
__device__ __forceinline__ uint32_t smem_u32(const void* p) {
    uint32_t a;
    asm("{ .reg .u64 t; cvta.to.shared.u64 t, %1; cvt.u32.u64 %0, t; }"
        : "=r"(a) : "l"(p));
    return a;
}
__device__ __forceinline__ void cp16(uint32_t dst, const void* src, bool v) {
    int sz = v ? 16 : 0;
    asm volatile("cp.async.cg.shared.global [%0], [%1], 16, %2;"
                 :: "r"(dst), "l"(src), "r"(sz) : "memory");
}
#define CP_COMMIT() asm volatile("cp.async.commit_group;" ::: "memory")
#define CP_WAIT1()  asm volatile("cp.async.wait_group 1;" ::: "memory")
#define CP_WAIT0()  asm volatile("cp.async.wait_group 0;" ::: "memory")

__device__ __forceinline__ void ldsm4(unsigned r[4], uint32_t a) {
    asm volatile("ldmatrix.sync.aligned.m8n8.x4.shared.b16 {%0,%1,%2,%3}, [%4];"
                 : "=r"(r[0]), "=r"(r[1]), "=r"(r[2]), "=r"(r[3]) : "r"(a));
}
__device__ __forceinline__ void ldsm4t(unsigned r[4], uint32_t a) {
    asm volatile("ldmatrix.sync.aligned.m8n8.x4.trans.shared.b16 {%0,%1,%2,%3}, [%4];"
                 : "=r"(r[0]), "=r"(r[1]), "=r"(r[2]), "=r"(r[3]) : "r"(a));
}

__device__ __forceinline__ void mma_tf32(float c[4], unsigned a0, unsigned a1,
                                         unsigned a2, unsigned a3,
                                         unsigned b0, unsigned b1)
{
    asm volatile(
        "mma.sync.aligned.m16n8k8.row.col.f32.tf32.tf32.f32 "
        "{%0,%1,%2,%3},{%4,%5,%6,%7},{%8,%9},{%0,%1,%2,%3};"
        : "+f"(c[0]), "+f"(c[1]), "+f"(c[2]), "+f"(c[3])
        : "r"(a0), "r"(a1), "r"(a2), "r"(a3), "r"(b0), "r"(b1));
}
__device__ __forceinline__ void mma_f16(float c[4], unsigned a0, unsigned a1,
                                        unsigned a2, unsigned a3,
                                        unsigned b0, unsigned b1)
{
    asm volatile(
        "mma.sync.aligned.m16n8k16.row.col.f32.f16.f16.f32 "
        "{%0,%1,%2,%3},{%4,%5,%6,%7},{%8,%9},{%0,%1,%2,%3};"
        : "+f"(c[0]), "+f"(c[1]), "+f"(c[2]), "+f"(c[3])
        : "r"(a0), "r"(a1), "r"(a2), "r"(a3), "r"(b0), "r"(b1));
}

// ---------------- LN stats ----------------
__global__ void __launch_bounds__(256) ln_stats(const float* __restrict__ x)
{
    int s = blockIdx.x * 256 + threadIdx.x;
    int b = blockIdx.y;
    const float* xp = x + (size_t)b * CHN * SP + s;
    float sum = 0.f, sumsq = 0.f;
    for (int c = 0; c < CHN; c++) { float v = xp[(size_t)c * SP]; sum += v; sumsq += v * v; }
    float mu = sum * (1.0f / CHN);
    float var = sumsq * (1.0f / CHN) - mu * mu;
    g_mu[(size_t)b * SP + s] = mu;
    g_rs[(size_t)b * SP + s] = rsqrtf(var + 1e-6f);
}

// ---------------- weight transpose+cvt [R][C] fp32 -> [C][R] fp16 ----------------
__global__ void __launch_bounds__(256) cvt_w_t(const float* __restrict__ in,
                                               __half* __restrict__ out, int R, int C)
{
    __shared__ float t[32][33];
    int c0 = blockIdx.x * 32, r0 = blockIdx.y * 32;
    int xl = threadIdx.x & 31, y = (threadIdx.x >> 5) * 4;
#pragma unroll
    for (int i = 0; i < 4; i++)
        t[y + i][xl] = in[(size_t)(r0 + y + i) * C + c0 + xl];
    __syncthreads();
#pragma unroll
    for (int i = 0; i < 4; i++)
        out[(size_t)(c0 + y + i) * R + r0 + xl] = __float2half_rn(t[xl][y + i]);
}

// ---------------- elementwise cvt ----------------
__global__ void __launch_bounds__(256) cvt16(const float* __restrict__ in,
                                             __half* __restrict__ out, int n)
{
    int i = blockIdx.x * 256 + threadIdx.x;
    if (i < n) out[i] = __float2half_rn(in[i]);
}

// ============ fused-LN Q GEMM: g_q = LN(hs) @ wq16^T ============
// A staged from raw hs [b][c][s]: LDG float4 (s-dir) -> normalize -> fp16 ->
// smem [k][m] pitch 136h; A-fragments via ldmatrix.x4.trans. B path = cp.async.
#define QA_SLOT 8704                    // 32*136*2
#define QB_OFF  17408                   // 2 A slots
#define QB_SLOT 10240
#define QSMEM   (QB_OFF + 3 * QB_SLOT)  // 48128

__global__ void __launch_bounds__(256)
gemm_q(const float* __restrict__ hs, const __half* __restrict__ Bt,
       float* __restrict__ Cout,
       const float* __restrict__ lw, const float* __restrict__ lb)
{
    extern __shared__ char smc[];
    uint32_t sb = smem_u32(smc);

    const int N = INNER, K = CHN, NT = K >> 5;
    int tid = threadIdx.x, lane = tid & 31, w = tid >> 5;
    int r = lane >> 2, q = lane & 3;
    int wm = w & 3, wn = w >> 2;
    int m0 = blockIdx.y * 128;
    int n0 = blockIdx.x * 128;
    int mb = wm * 32, nb = wn * 64;

    int b = m0 >> 12, s0 = m0 & (SP - 1);
    const float* Abase = hs + (size_t)b * CHN * SP + s0;

    // per-thread LN constants (m-group fixed for loader)
    int mgrp = (lane) * 4;              // loader handles m = mgrp..mgrp+3
    int krow = tid >> 5;                // k = krow + 8i
    float4 mu4 = *(const float4*)(g_mu + m0 + mgrp);
    float4 rs4 = *(const float4*)(g_rs + m0 + mgrp);

    // ldmatrix offsets
    uint32_t offA = (uint32_t)((lane & 7) + ((lane & 16) ? 8 : 0)) * 272
                  + (uint32_t)(mb + ((lane & 8) ? 8 : 0)) * 2;
    uint32_t offB = (uint32_t)((nb + (lane & 7) + ((lane & 16) ? 8 : 0)) * 40
                               + ((lane & 8) ? 8 : 0)) * 2;

    float acc[2][8][4];
#pragma unroll
    for (int i = 0; i < 2; i++)
#pragma unroll
        for (int j = 0; j < 8; j++)
#pragma unroll
            for (int l = 0; l < 4; l++) acc[i][j][l] = 0.f;

    auto loadB = [&](int slot, int k0) {
        uint32_t st = sb + QB_OFF + slot * QB_SLOT;
#pragma unroll
        for (int i = 0; i < 2; i++) {
            int cid = tid + i * 256;
            int row = cid >> 2, ch = cid & 3;
            cp16(st + row * 80 + ch * 16,
                 Bt + (size_t)(n0 + row) * K + k0 + ch * 8, true);
        }
    };

    uint2 st[4];
    auto ldgA = [&](int k0) {
#pragma unroll
        for (int i = 0; i < 4; i++) {
            int k = krow + 8 * i;
            float4 v = *(const float4*)(Abase + (size_t)(k0 + k) * SP + mgrp);
            float wv = __ldg(lw + k0 + k), bv = __ldg(lb + k0 + k);
            __half2 h0 = __floats2half2_rn((v.x - mu4.x) * rs4.x * wv + bv,
                                           (v.y - mu4.y) * rs4.y * wv + bv);
            __half2 h1 = __floats2half2_rn((v.z - mu4.z) * rs4.z * wv + bv,
                                           (v.w - mu4.w) * rs4.w * wv + bv);
            st[i].x = *(unsigned*)&h0;
            st[i].y = *(unsigned*)&h1;
        }
    };
    auto stsA = [&](int slot) {
        char* At = smc + slot * QA_SLOT;
#pragma unroll
        for (int i = 0; i < 4; i++) {
            int k = krow + 8 * i;
            *(uint2*)(At + k * 272 + mgrp * 2) = st[i];
        }
    };

    loadB(0, 0);  CP_COMMIT();
    loadB(1, 32); CP_COMMIT();
    ldgA(0);

    for (int t = 0; t < NT; t++) {
        stsA(t & 1);
        if (t == NT - 1) CP_WAIT0(); else CP_WAIT1();
        __syncthreads();
        if (t + 2 < NT) { loadB((t + 2) % 3, (t + 2) * 32); CP_COMMIT(); }
        if (t + 1 < NT) ldgA((t + 1) * 32);

        uint32_t aBase = sb + (t & 1) * QA_SLOT + offA;
        uint32_t bBase = sb + QB_OFF + (t % 3) * QB_SLOT + offB;

        unsigned ac[2][4], an[2][4];
        ldsm4t(ac[0], aBase);            // m-tile 0, k 0..15
        ldsm4t(ac[1], aBase + 32);       // m-tile 1 (cols +16 halves)
#pragma unroll
        for (int kc = 0; kc < 2; kc++) {
            if (kc == 0) {
                ldsm4t(an[0], aBase + 16 * 272);      // k 16..31
                ldsm4t(an[1], aBase + 16 * 272 + 32);
            }
            unsigned bb[4][4];
#pragma unroll
            for (int j = 0; j < 4; j++)
                ldsm4(bb[j], bBase + j * 1280 + kc * 32);
#pragma unroll
            for (int j = 0; j < 4; j++) {
#pragma unroll
                for (int im = 0; im < 2; im++)
                    mma_f16(acc[im][2 * j], ac[im][0], ac[im][1], ac[im][2],
                            ac[im][3], bb[j][0], bb[j][1]);
#pragma unroll
                for (int im = 0; im < 2; im++)
                    mma_f16(acc[im][2 * j + 1], ac[im][0], ac[im][1], ac[im][2],
                            ac[im][3], bb[j][2], bb[j][3]);
            }
            if (kc == 0) {
#pragma unroll
                for (int im = 0; im < 2; im++)
#pragma unroll
                    for (int jj = 0; jj < 4; jj++) ac[im][jj] = an[im][jj];
            }
        }
        __syncthreads();   // before next iter's stsA overwrites slot (t+1)&1
    }

    // -------- epilogue (EPI 0) --------
    float* Cs = (float*)smc;
#pragma unroll 1
    for (int ch = 0; ch < 4; ch++) {
        __syncthreads();
        if (wm == ch) {
#pragma unroll
            for (int im = 0; im < 2; im++) {
                int r0 = im * 16 + r;
#pragma unroll
                for (int in_ = 0; in_ < 8; in_++) {
                    int cc = nb + in_ * 8 + q * 2;
                    Cs[r0 * 132 + cc]           = acc[im][in_][0];
                    Cs[r0 * 132 + cc + 1]       = acc[im][in_][1];
                    Cs[(r0 + 8) * 132 + cc]     = acc[im][in_][2];
                    Cs[(r0 + 8) * 132 + cc + 1] = acc[im][in_][3];
                }
            }
        }
        __syncthreads();
        for (int t = tid; t < 32 * 128; t += 256) {
            int ml = t >> 7, n = t & 127;
            int m = m0 + ch * 32 + ml;
            Cout[(size_t)m * N + n0 + n] = Cs[ml * 132 + n];
        }
    }
}

// ---------------- fp16 mma GEMM (KV, O): D = A[M][K] * Bt[N][K]^T ----------------
#define HBOFF  10240
#define HSTG   20480
#define HGSMEM (3 * HSTG)

template<int EPI, bool MG>
__global__ void __launch_bounds__(256, 2)
gemm_h(const __half* __restrict__ A, const __half* __restrict__ Bt,
       float* __restrict__ Cout, int M, int N, int K, int lda,
       const float* __restrict__ bias, const float* __restrict__ resid)
{
    extern __shared__ char smc[];
    uint32_t sb = smem_u32(smc);

    int tid = threadIdx.x, lane = tid & 31, w = tid >> 5;
    int r = lane >> 2, q = lane & 3;
    int wm = w & 3, wn = w >> 2;
    int m0 = blockIdx.y * 128;
    int n0 = blockIdx.x * 128;
    int mb = wm * 32, nb = wn * 64;
    int NT = K >> 5;

    uint32_t offA = (uint32_t)((mb + (lane & 15)) * 40 + ((lane & 16) ? 8 : 0)) * 2;
    uint32_t offB = (uint32_t)((nb + (lane & 7) + ((lane & 16) ? 8 : 0)) * 40
                               + ((lane & 8) ? 8 : 0)) * 2;

    float acc[2][8][4];
#pragma unroll
    for (int i = 0; i < 2; i++)
#pragma unroll
        for (int j = 0; j < 8; j++)
#pragma unroll
            for (int l = 0; l < 4; l++) acc[i][j][l] = 0.f;

    auto load_stage = [&](int slot, int k0) {
        uint32_t st = sb + slot * HSTG;
#pragma unroll
        for (int i = 0; i < 2; i++) {
            int cid = tid + i * 256;
            int row = cid >> 2, ch = cid & 3;
            bool v = !MG || (m0 + row) < M;
            cp16(st + row * 80 + ch * 16,
                 A + (size_t)(m0 + row) * lda + k0 + ch * 8, v);
        }
#pragma unroll
        for (int i = 0; i < 2; i++) {
            int cid = tid + i * 256;
            int row = cid >> 2, ch = cid & 3;
            cp16(st + HBOFF + row * 80 + ch * 16,
                 Bt + (size_t)(n0 + row) * K + k0 + ch * 8, true);
        }
    };

    load_stage(0, 0);  CP_COMMIT();
    load_stage(1, 32); CP_COMMIT();

    for (int t = 0; t < NT; t++) {
        if (t == NT - 1) CP_WAIT0(); else CP_WAIT1();
        __syncthreads();
        if (t + 2 < NT) { load_stage((t + 2) % 3, (t + 2) * 32); CP_COMMIT(); }

        int slot = t % 3;
        uint32_t aBase = sb + slot * HSTG + offA;
        uint32_t bBase = sb + slot * HSTG + HBOFF + offB;

        unsigned ac[2][4], an[2][4];
        ldsm4(ac[0], aBase);
        ldsm4(ac[1], aBase + 1280);
#pragma unroll
        for (int kc = 0; kc < 2; kc++) {
            if (kc == 0) {
                ldsm4(an[0], aBase + 32);
                ldsm4(an[1], aBase + 1280 + 32);
            }
            unsigned bb[4][4];
#pragma unroll
            for (int j = 0; j < 4; j++)
                ldsm4(bb[j], bBase + j * 1280 + kc * 32);
#pragma unroll
            for (int j = 0; j < 4; j++) {
#pragma unroll
                for (int im = 0; im < 2; im++)
                    mma_f16(acc[im][2 * j], ac[im][0], ac[im][1], ac[im][2],
                            ac[im][3], bb[j][0], bb[j][1]);
#pragma unroll
                for (int im = 0; im < 2; im++)
                    mma_f16(acc[im][2 * j + 1], ac[im][0], ac[im][1], ac[im][2],
                            ac[im][3], bb[j][2], bb[j][3]);
            }
            if (kc == 0) {
#pragma unroll
                for (int im = 0; im < 2; im++)
#pragma unroll
                    for (int jj = 0; jj < 4; jj++) ac[im][jj] = an[im][jj];
            }
        }
    }
    __syncthreads();

    // -------- epilogue --------
    float* Cs = (float*)smc;
    if (EPI == 0) {
#pragma unroll 1
        for (int ch = 0; ch < 4; ch++) {
            __syncthreads();
            if (wm == ch) {
#pragma unroll
                for (int im = 0; im < 2; im++) {
                    int r0 = im * 16 + r;
#pragma unroll
                    for (int in_ = 0; in_ < 8; in_++) {
                        int cc = nb + in_ * 8 + q * 2;
                        Cs[r0 * 132 + cc]           = acc[im][in_][0];
                        Cs[r0 * 132 + cc + 1]       = acc[im][in_][1];
                        Cs[(r0 + 8) * 132 + cc]     = acc[im][in_][2];
                        Cs[(r0 + 8) * 132 + cc + 1] = acc[im][in_][3];
                    }
                }
            }
            __syncthreads();
            for (int t = tid; t < 32 * 128; t += 256) {
                int ml = t >> 7, n = t & 127;
                int m = m0 + ch * 32 + ml;
                if (MG && m >= M) continue;
                Cout[(size_t)m * N + n0 + n] = Cs[ml * 132 + n];
            }
        }
    } else {
#pragma unroll 1
        for (int ch = 0; ch < 4; ch++) {
            __syncthreads();
            if (wn == (ch >> 1)) {
                int inlo = (ch & 1) * 4;
#pragma unroll
                for (int im = 0; im < 2; im++) {
                    int mrow = mb + im * 16 + r;
#pragma unroll
                    for (int ii = 0; ii < 4; ii++) {
                        int in_ = inlo + ii;
                        int nl = in_ * 8 + q * 2 - (ch & 1) * 32;
                        Cs[nl * 132 + mrow]           = acc[im][in_][0];
                        Cs[(nl + 1) * 132 + mrow]     = acc[im][in_][1];
                        Cs[nl * 132 + mrow + 8]       = acc[im][in_][2];
                        Cs[(nl + 1) * 132 + mrow + 8] = acc[im][in_][3];
                    }
                }
            }
            __syncthreads();
            for (int t = tid; t < 32 * 128; t += 256) {
                int nl = t >> 7, ml = t & 127;
                int n = n0 + ch * 32 + nl;
                int m = m0 + ml;
                int b = m >> 12, s = m & (SP - 1);
                size_t addr = (size_t)b * CHN * SP + (size_t)n * SP + s;
                Cout[addr] = Cs[nl * 132 + ml] + bias[n] + resid[addr];
            }
        }
    }
}

// ---------------- tensor-core attention (tf32), half2 output ----------------
#define AT_SMEM 55040

__global__ void __launch_bounds__(256, 2) attn_mma()
{
    extern __shared__ float sm[];
    float* Ks = sm;              // [80][84]
    float* Vs = sm + 6720;       // [80][88]

    int tid = threadIdx.x, lane = tid & 31, w = tid >> 5;
    int b = blockIdx.z, h = blockIdx.y;
    int q0 = blockIdx.x * 128;
    int mb = w * 16;
    int r = lane >> 2, q = lane & 3, q2 = q * 2;
    uint32_t sb = smem_u32(sm);

    const float* kg = g_k + (size_t)b * TT * INNER + h * HDIM;
    const float* vg = g_v + (size_t)b * TT * INNER + h * HDIM;

#pragma unroll
    for (int i = 0; i < 7; i++) {
        int cid = tid + i * 256;
        if (cid < 1540) {
            int row = cid / 20, ch = cid % 20;
            cp16(sb + (row * 84 + ch * 4) * 4, kg + (size_t)row * INNER + ch * 4, true);
            cp16(sb + (6720 + row * 88 + ch * 4) * 4, vg + (size_t)row * INNER + ch * 4, true);
        }
    }
    CP_COMMIT();

    const float* qg = g_q + ((size_t)b * SP + q0 + mb) * INNER + h * HDIM;
    float qf[10][4];
#pragma unroll
    for (int k8 = 0; k8 < 10; k8++) {
        int c = k8 * 8 + q;
        qf[k8][0] = qg[(size_t)r * INNER + c];
        qf[k8][1] = qg[(size_t)(r + 8) * INNER + c];
        qf[k8][2] = qg[(size_t)r * INNER + c + 4];
        qf[k8][3] = qg[(size_t)(r + 8) * INNER + c + 4];
    }

    if (tid < 240) {
        int row = 77 + tid / 80, col = tid % 80;
        Ks[row * 84 + col] = 0.f;
        Vs[row * 88 + col] = 0.f;
    }
    CP_WAIT0();
    __syncthreads();

    float acc[10][4];
#pragma unroll
    for (int i = 0; i < 10; i++)
#pragma unroll
        for (int j = 0; j < 4; j++) acc[i][j] = 0.f;

#pragma unroll
    for (int k8 = 0; k8 < 10; k8++) {
        int kr = k8 * 8 + q;
        unsigned a0 = __float_as_uint(qf[k8][0]);
        unsigned a1 = __float_as_uint(qf[k8][1]);
        unsigned a2 = __float_as_uint(qf[k8][2]);
        unsigned a3 = __float_as_uint(qf[k8][3]);
#pragma unroll
        for (int in_ = 0; in_ < 10; in_++) {
            int tcol = in_ * 8 + r;
            unsigned b0 = __float_as_uint(Ks[tcol * 84 + kr]);
            unsigned b1 = __float_as_uint(Ks[tcol * 84 + kr + 4]);
            mma_tf32(acc[in_], a0, a1, a2, a3, b0, b1);
        }
    }

    const float scale = 0.11180339887498949f;
    float invs[2];
#pragma unroll
    for (int hf = 0; hf < 2; hf++) {
        float mx = -1e30f;
#pragma unroll
        for (int in_ = 0; in_ < 10; in_++) {
            int c0 = in_ * 8 + q2;
            float v0 = (c0     < TT) ? acc[in_][hf * 2]     * scale : -1e30f;
            float v1 = (c0 + 1 < TT) ? acc[in_][hf * 2 + 1] * scale : -1e30f;
            acc[in_][hf * 2] = v0; acc[in_][hf * 2 + 1] = v1;
            mx = fmaxf(mx, fmaxf(v0, v1));
        }
        mx = fmaxf(mx, __shfl_xor_sync(0xffffffffu, mx, 1));
        mx = fmaxf(mx, __shfl_xor_sync(0xffffffffu, mx, 2));
        float s = 0.f;
#pragma unroll
        for (int in_ = 0; in_ < 10; in_++) {
            int c0 = in_ * 8 + q2;
            float e0 = (c0     < TT) ? __expf(acc[in_][hf * 2]     - mx) : 0.f;
            float e1 = (c0 + 1 < TT) ? __expf(acc[in_][hf * 2 + 1] - mx) : 0.f;
            acc[in_][hf * 2] = e0; acc[in_][hf * 2 + 1] = e1;
            s += e0 + e1;
        }
        s += __shfl_xor_sync(0xffffffffu, s, 1);
        s += __shfl_xor_sync(0xffffffffu, s, 2);
        invs[hf] = 1.f / s;
    }

    float oc[10][4];
#pragma unroll
    for (int i = 0; i < 10; i++)
#pragma unroll
        for (int j = 0; j < 4; j++) oc[i][j] = 0.f;

    int S0 = (r << 2) | (q >> 1);
    int S2 = S0 + 2;
    bool odd = (q & 1) != 0;
#pragma unroll
    for (int k8 = 0; k8 < 10; k8++) {
        float v0 = __shfl_sync(0xffffffffu, acc[k8][0], S0);
        float v1 = __shfl_sync(0xffffffffu, acc[k8][1], S0);
        float v2 = __shfl_sync(0xffffffffu, acc[k8][2], S0);
        float v3 = __shfl_sync(0xffffffffu, acc[k8][3], S0);
        float u0 = __shfl_sync(0xffffffffu, acc[k8][0], S2);
        float u1 = __shfl_sync(0xffffffffu, acc[k8][1], S2);
        float u2 = __shfl_sync(0xffffffffu, acc[k8][2], S2);
        float u3 = __shfl_sync(0xffffffffu, acc[k8][3], S2);
        unsigned a0 = __float_as_uint(odd ? v1 : v0);
        unsigned a1 = __float_as_uint(odd ? v3 : v2);
        unsigned a2 = __float_as_uint(odd ? u1 : u0);
        unsigned a3 = __float_as_uint(odd ? u3 : u2);
        int kr = k8 * 8 + q;
#pragma unroll
        for (int in_ = 0; in_ < 10; in_++) {
            int ncol = in_ * 8 + r;
            unsigned b0 = __float_as_uint(Vs[kr * 88 + ncol]);
            unsigned b1 = __float_as_uint(Vs[(kr + 4) * 88 + ncol]);
            mma_tf32(oc[in_], a0, a1, a2, a3, b0, b1);
        }
    }

    __half* og = g_at16 + ((size_t)b * SP + q0 + mb) * INNER + h * HDIM;
#pragma unroll
    for (int in_ = 0; in_ < 10; in_++) {
        int c = in_ * 8 + q2;
        *(__half2*)(og + (size_t)r * INNER + c) =
            __floats2half2_rn(oc[in_][0] * invs[0], oc[in_][1] * invs[0]);
        *(__half2*)(og + (size_t)(r + 8) * INNER + c) =
            __floats2half2_rn(oc[in_][2] * invs[1], oc[in_][3] * invs[1]);
    }
}

// ---------------- launch ----------------
extern "C" void kernel_launch(void* const* d_in, const int* in_sizes, int n_in,
                              void* d_out, int out_size)
{
    (void)in_sizes; (void)n_in; (void)out_size;
    const float* hs  = (const float*)d_in[0];
    const float* enc = (const float*)d_in[1];
    const float* lnw = (const float*)d_in[2];
    const float* lnb = (const float*)d_in[3];
    const float* wq  = (const float*)d_in[4];
    const float* wk  = (const float*)d_in[5];
    const float* wv  = (const float*)d_in[6];
    const float* wo  = (const float*)d_in[7];
    const float* bo  = (const float*)d_in[8];
    float* out = (float*)d_out;

    float *p_q, *p_k, *p_v;
    __half *p_at16, *p_e16, *p_wq16, *p_wk16, *p_wv16, *p_wo16;
    cudaGetSymbolAddress((void**)&p_q,    g_q);
    cudaGetSymbolAddress((void**)&p_k,    g_k);
    cudaGetSymbolAddress((void**)&p_v,    g_v);
    cudaGetSymbolAddress((void**)&p_at16, g_at16);
    cudaGetSymbolAddress((void**)&p_e16,  g_e16);
    cudaGetSymbolAddress((void**)&p_wq16, g_wq16);
    cudaGetSymbolAddress((void**)&p_wk16, g_wk16);
    cudaGetSymbolAddress((void**)&p_wv16, g_wv16);
    cudaGetSymbolAddress((void**)&p_wo16, g_wo16);

    cudaFuncSetAttribute(gemm_q,
                         cudaFuncAttributeMaxDynamicSharedMemorySize, QSMEM);
    cudaFuncSetAttribute(gemm_h<0, true>,
                         cudaFuncAttributeMaxDynamicSharedMemorySize, HGSMEM);
    cudaFuncSetAttribute(gemm_h<1, false>,
                         cudaFuncAttributeMaxDynamicSharedMemorySize, HGSMEM);
    cudaFuncSetAttribute(attn_mma,
                         cudaFuncAttributeMaxDynamicSharedMemorySize, AT_SMEM);

    // one-time fp16 conversions
    cvt_w_t<<<dim3(INNER / 32, CHN / 32), 256>>>(wq, p_wq16, CHN, INNER);
    cvt_w_t<<<dim3(INNER / 32, XDIM / 32), 256>>>(wk, p_wk16, XDIM, INNER);
    cvt_w_t<<<dim3(INNER / 32, XDIM / 32), 256>>>(wv, p_wv16, XDIM, INNER);
    cvt_w_t<<<dim3(CHN / 32, INNER / 32), 256>>>(wo, p_wo16, INNER, CHN);
    {
        int n = BATCH * TT * XDIM;
        cvt16<<<(n + 255) / 256, 256>>>(enc, p_e16, n);
    }

    // LN stats
    ln_stats<<<dim3(SP / 256, BATCH), 256>>>(hs);

    // Q = LN(hs) @ wq16^T, normalization fused into the A loader
    gemm_q<<<dim3(INNER / 128, (BATCH * SP) / 128), 256, QSMEM>>>(
        hs, p_wq16, p_q, lnw, lnb);

    // K, V = e16 @ w^T   (M = 1232, guarded)
    int mkv = (BATCH * TT + 127) / 128;
    gemm_h<0, true><<<dim3(INNER / 128, mkv), 256, HGSMEM>>>(
        p_e16, p_wk16, p_k, BATCH * TT, INNER, XDIM, XDIM, nullptr, nullptr);
    gemm_h<0, true><<<dim3(INNER / 128, mkv), 256, HGSMEM>>>(
        p_e16, p_wv16, p_v, BATCH * TT, INNER, XDIM, XDIM, nullptr, nullptr);

    // attention (tf32 tensor-core)
    attn_mma<<<dim3(SP / 128, NHE, BATCH), 256, AT_SMEM>>>();

    // out = at16 @ wo16^T + bo + residual (transposed store, fp32)
    gemm_h<1, false><<<dim3(CHN / 128, (BATCH * SP) / 128), 256, HGSMEM>>>(
        p_at16, p_wo16, out, BATCH * SP, CHN, INNER, INNER, bo, hs);
}

// round 12
// speedup vs baseline: 1.0756x; 1.0756x over previous
#include <cuda_runtime.h>
#include <cuda_fp16.h>
#include <math.h>
#include <stdint.h>

#define BATCH 16
#define CHN   640
#define SP    4096
#define TT    77
#define XDIM  768
#define NHE   8
#define HDIM  80
#define INNER 640

// ---------------- scratch ----------------
__device__ float  g_q   [(size_t)BATCH * SP * INNER];   // fp32 (attn input)
__device__ float  g_k   [(size_t)BATCH * TT * INNER];
__device__ float  g_v   [(size_t)BATCH * TT * INNER];
__device__ __half g_x16 [(size_t)BATCH * SP * CHN];     // LN(hs) [b][s][c]
__device__ __half g_at16[(size_t)BATCH * SP * INNER];   // attn out
__device__ __half g_e16 [(size_t)BATCH * TT * XDIM];
__device__ __half g_wq16[(size_t)INNER * CHN];          // [N][K]
__device__ __half g_wk16[(size_t)INNER * XDIM];
__device__ __half g_wv16[(size_t)INNER * XDIM];
__device__ __half g_wo16[(size_t)CHN * INNER];
__device__ float  g_mu  [(size_t)BATCH * SP];
__device__ float  g_rs  [(size_t)BATCH * SP];

// ---------------- helpers ----------------
__device__ __forceinline__ uint32_t smem_u32(const void* p) {
    uint32_t a;
    asm("{ .reg .u64 t; cvta.to.shared.u64 t, %1; cvt.u32.u64 %0, t; }"
        : "=r"(a) : "l"(p));
    return a;
}
__device__ __forceinline__ void cp16(uint32_t dst, const void* src, bool v) {
    int sz = v ? 16 : 0;
    asm volatile("cp.async.cg.shared.global [%0], [%1], 16, %2;"
                 :: "r"(dst), "l"(src), "r"(sz) : "memory");
}
#define CP_COMMIT() asm volatile("cp.async.commit_group;" ::: "memory")
#define CP_WAIT1()  asm volatile("cp.async.wait_group 1;" ::: "memory")
#define CP_WAIT0()  asm volatile("cp.async.wait_group 0;" ::: "memory")

__device__ __forceinline__ void ldsm4(unsigned r[4], uint32_t a) {
    asm volatile("ldmatrix.sync.aligned.m8n8.x4.shared.b16 {%0,%1,%2,%3}, [%4];"
                 : "=r"(r[0]), "=r"(r[1]), "=r"(r[2]), "=r"(r[3]) : "r"(a));
}
__device__ __forceinline__ void ldsm4t(unsigned r[4], uint32_t a) {
    asm volatile("ldmatrix.sync.aligned.m8n8.x4.trans.shared.b16 {%0,%1,%2,%3}, [%4];"
                 : "=r"(r[0]), "=r"(r[1]), "=r"(r[2]), "=r"(r[3]) : "r"(a));
}

__device__ __forceinline__ void mma_f16(float c[4], unsigned a0, unsigned a1,
                                        unsigned a2, unsigned a3,
                                        unsigned b0, unsigned b1)
{
    asm volatile(
        "mma.sync.aligned.m16n8k16.row.col.f32.f16.f16.f32 "
        "{%0,%1,%2,%3},{%4,%5,%6,%7},{%8,%9},{%0,%1,%2,%3};"
        : "+f"(c[0]), "+f"(c[1]), "+f"(c[2]), "+f"(c[3])
        : "r"(a0), "r"(a1), "r"(a2), "r"(a3), "r"(b0), "r"(b1));
}

// ---------------- LN stats ----------------
__global__ void __launch_bounds__(256) ln_stats(const float* __restrict__ x)
{
    int s = blockIdx.x * 256 + threadIdx.x;
    int b = blockIdx.y;
    const float* xp = x + (size_t)b * CHN * SP + s;
    float sum = 0.f, sumsq = 0.f;
    for (int c = 0; c < CHN; c++) { float v = xp[(size_t)c * SP]; sum += v; sumsq += v * v; }
    float mu = sum * (1.0f / CHN);
    float var = sumsq * (1.0f / CHN) - mu * mu;
    g_mu[(size_t)b * SP + s] = mu;
    g_rs[(size_t)b * SP + s] = rsqrtf(var + 1e-6f);
}

// ---------------- normalize + transpose -> fp16 [b][s][c] ----------------
__global__ void __launch_bounds__(256) ln_t16(const float* __restrict__ x,
                                              const float* __restrict__ lw,
                                              const float* __restrict__ lb)
{
    __shared__ float t[32][33];
    int s0 = blockIdx.x * 32, c0 = blockIdx.y * 32, b = blockIdx.z;
    int xl = threadIdx.x & 31, y = (threadIdx.x >> 5) * 4;
#pragma unroll
    for (int i = 0; i < 4; i++)
        t[y + i][xl] = x[((size_t)b * CHN + c0 + y + i) * SP + s0 + xl];
    __syncthreads();
    float wv = lw[c0 + xl], bv = lb[c0 + xl];
#pragma unroll
    for (int i = 0; i < 4; i++) {
        int s = s0 + y + i;
        float mu = g_mu[(size_t)b * SP + s];
        float rs = g_rs[(size_t)b * SP + s];
        float v = (t[xl][y + i] - mu) * rs * wv + bv;
        g_x16[((size_t)b * SP + s) * CHN + c0 + xl] = __float2half_rn(v);
    }
}

// ---------------- weight transpose+cvt [R][C] fp32 -> [C][R] fp16 ----------------
__global__ void __launch_bounds__(256) cvt_w_t(const float* __restrict__ in,
                                               __half* __restrict__ out, int R, int C)
{
    __shared__ float t[32][33];
    int c0 = blockIdx.x * 32, r0 = blockIdx.y * 32;
    int xl = threadIdx.x & 31, y = (threadIdx.x >> 5) * 4;
#pragma unroll
    for (int i = 0; i < 4; i++)
        t[y + i][xl] = in[(size_t)(r0 + y + i) * C + c0 + xl];
    __syncthreads();
#pragma unroll
    for (int i = 0; i < 4; i++)
        out[(size_t)(c0 + y + i) * R + r0 + xl] = __float2half_rn(t[xl][y + i]);
}

// ---------------- elementwise cvt ----------------
__global__ void __launch_bounds__(256) cvt16(const float* __restrict__ in,
                                             __half* __restrict__ out, int n)
{
    int i = blockIdx.x * 256 + threadIdx.x;
    if (i < n) out[i] = __float2half_rn(in[i]);
}

// ---------------- fp16 mma GEMM: D = A[M][K] * Bt[N][K]^T ----------------
// 3-stage cp.async pipeline; fragments via ldmatrix.x4 (conflict-free, pitch 40h).
// EPI 0: C[m][n] fp32;  EPI 1: out[b][n][s] fp32 + bias + resid
#define HBOFF  10240
#define HSTG   20480
#define HGSMEM (3 * HSTG)

template<int EPI, bool MG>
__global__ void __launch_bounds__(256, 2)
gemm_h(const __half* __restrict__ A, const __half* __restrict__ Bt,
       float* __restrict__ Cout, int M, int N, int K, int lda,
       const float* __restrict__ bias, const float* __restrict__ resid)
{
    extern __shared__ char smc[];
    uint32_t sb = smem_u32(smc);

    int tid = threadIdx.x, lane = tid & 31, w = tid >> 5;
    int r = lane >> 2, q = lane & 3;
    int wm = w & 3, wn = w >> 2;
    int m0 = blockIdx.y * 128;
    int n0 = blockIdx.x * 128;
    int mb = wm * 32, nb = wn * 64;
    int NT = K >> 5;

    uint32_t offA = (uint32_t)((mb + (lane & 15)) * 40 + ((lane & 16) ? 8 : 0)) * 2;
    uint32_t offB = (uint32_t)((nb + (lane & 7) + ((lane & 16) ? 8 : 0)) * 40
                               + ((lane & 8) ? 8 : 0)) * 2;

    float acc[2][8][4];
#pragma unroll
    for (int i = 0; i < 2; i++)
#pragma unroll
        for (int j = 0; j < 8; j++)
#pragma unroll
            for (int l = 0; l < 4; l++) acc[i][j][l] = 0.f;

    auto load_stage = [&](int slot, int k0) {
        uint32_t st = sb + slot * HSTG;
#pragma unroll
        for (int i = 0; i < 2; i++) {
            int cid = tid + i * 256;
            int row = cid >> 2, ch = cid & 3;
            bool v = !MG || (m0 + row) < M;
            cp16(st + row * 80 + ch * 16,
                 A + (size_t)(m0 + row) * lda + k0 + ch * 8, v);
        }
#pragma unroll
        for (int i = 0; i < 2; i++) {
            int cid = tid + i * 256;
            int row = cid >> 2, ch = cid & 3;
            cp16(st + HBOFF + row * 80 + ch * 16,
                 Bt + (size_t)(n0 + row) * K + k0 + ch * 8, true);
        }
    };

    load_stage(0, 0);  CP_COMMIT();
    load_stage(1, 32); CP_COMMIT();

    for (int t = 0; t < NT; t++) {
        if (t == NT - 1) CP_WAIT0(); else CP_WAIT1();
        __syncthreads();
        if (t + 2 < NT) { load_stage((t + 2) % 3, (t + 2) * 32); CP_COMMIT(); }

        int slot = t % 3;
        uint32_t aBase = sb + slot * HSTG + offA;
        uint32_t bBase = sb + slot * HSTG + HBOFF + offB;

        unsigned ac[2][4], an[2][4];
        ldsm4(ac[0], aBase);
        ldsm4(ac[1], aBase + 1280);
#pragma unroll
        for (int kc = 0; kc < 2; kc++) {
            if (kc == 0) {
                ldsm4(an[0], aBase + 32);
                ldsm4(an[1], aBase + 1280 + 32);
            }
            unsigned bb[4][4];
#pragma unroll
            for (int j = 0; j < 4; j++)
                ldsm4(bb[j], bBase + j * 1280 + kc * 32);
#pragma unroll
            for (int j = 0; j < 4; j++) {
#pragma unroll
                for (int im = 0; im < 2; im++)
                    mma_f16(acc[im][2 * j], ac[im][0], ac[im][1], ac[im][2],
                            ac[im][3], bb[j][0], bb[j][1]);
#pragma unroll
                for (int im = 0; im < 2; im++)
                    mma_f16(acc[im][2 * j + 1], ac[im][0], ac[im][1], ac[im][2],
                            ac[im][3], bb[j][2], bb[j][3]);
            }
            if (kc == 0) {
#pragma unroll
                for (int im = 0; im < 2; im++)
#pragma unroll
                    for (int jj = 0; jj < 4; jj++) ac[im][jj] = an[im][jj];
            }
        }
    }
    __syncthreads();

    // -------- epilogue --------
    float* Cs = (float*)smc;
    if (EPI == 0) {
#pragma unroll 1
        for (int ch = 0; ch < 4; ch++) {
            __syncthreads();
            if (wm == ch) {
#pragma unroll
                for (int im = 0; im < 2; im++) {
                    int r0 = im * 16 + r;
#pragma unroll
                    for (int in_ = 0; in_ < 8; in_++) {
                        int cc = nb + in_ * 8 + q * 2;
                        Cs[r0 * 132 + cc]           = acc[im][in_][0];
                        Cs[r0 * 132 + cc + 1]       = acc[im][in_][1];
                        Cs[(r0 + 8) * 132 + cc]     = acc[im][in_][2];
                        Cs[(r0 + 8) * 132 + cc + 1] = acc[im][in_][3];
                    }
                }
            }
            __syncthreads();
            for (int t = tid; t < 32 * 128; t += 256) {
                int ml = t >> 7, n = t & 127;
                int m = m0 + ch * 32 + ml;
                if (MG && m >= M) continue;
                Cout[(size_t)m * N + n0 + n] = Cs[ml * 132 + n];
            }
        }
    } else {
#pragma unroll 1
        for (int ch = 0; ch < 4; ch++) {
            __syncthreads();
            if (wn == (ch >> 1)) {
                int inlo = (ch & 1) * 4;
#pragma unroll
                for (int im = 0; im < 2; im++) {
                    int mrow = mb + im * 16 + r;
#pragma unroll
                    for (int ii = 0; ii < 4; ii++) {
                        int in_ = inlo + ii;
                        int nl = in_ * 8 + q * 2 - (ch & 1) * 32;
                        Cs[nl * 132 + mrow]           = acc[im][in_][0];
                        Cs[(nl + 1) * 132 + mrow]     = acc[im][in_][1];
                        Cs[nl * 132 + mrow + 8]       = acc[im][in_][2];
                        Cs[(nl + 1) * 132 + mrow + 8] = acc[im][in_][3];
                    }
                }
            }
            __syncthreads();
            for (int t = tid; t < 32 * 128; t += 256) {
                int nl = t >> 7, ml = t & 127;
                int n = n0 + ch * 32 + nl;
                int m = m0 + ml;
                int b = m >> 12, s = m & (SP - 1);
                size_t addr = (size_t)b * CHN * SP + (size_t)n * SP + s;
                Cout[addr] = Cs[nl * 132 + ml] + bias[n] + resid[addr];
            }
        }
    }
}

// ---------------- fp16 tensor-core attention ----------------
// K,V staged fp16 [t][d] rows (pitch 88h). QK B-frags: ldsm4 on K.
// PV B-frags: ldsm4t on V (transpose inside ldmatrix). P-frags straight
// from S accumulators. 28,160B smem -> 2 CTAs/SM.
#define AT_SMEM 28160

__global__ void __launch_bounds__(256, 2) attn_mma()
{
    extern __shared__ __half smh[];
    __half* Kh = smh;            // [80][88]
    __half* Vh = smh + 7040;     // [80][88]

    int tid = threadIdx.x, lane = tid & 31, w = tid >> 5;
    int b = blockIdx.z, h = blockIdx.y;
    int q0 = blockIdx.x * 128;
    int mb = w * 16;
    int r = lane >> 2, q = lane & 3, q2 = q * 2;
    uint32_t sb = smem_u32(smh);

    const float* kg = g_k + (size_t)b * TT * INNER + h * HDIM;
    const float* vg = g_v + (size_t)b * TT * INNER + h * HDIM;

    // stage K,V: fp32 float4 -> half2 pairs, coalesced 8B STS
#pragma unroll
    for (int i = 0; i < 7; i++) {
        int cid = tid + i * 256;
        if (cid < 1540) {
            int t = cid / 20, d4 = cid % 20;
            float4 kv = *(const float4*)(kg + (size_t)t * INNER + d4 * 4);
            float4 vv = *(const float4*)(vg + (size_t)t * INNER + d4 * 4);
            __half2 k0 = __floats2half2_rn(kv.x, kv.y);
            __half2 k1 = __floats2half2_rn(kv.z, kv.w);
            __half2 v0 = __floats2half2_rn(vv.x, vv.y);
            __half2 v1 = __floats2half2_rn(vv.z, vv.w);
            uint2 ks, vs;
            ks.x = *(unsigned*)&k0; ks.y = *(unsigned*)&k1;
            vs.x = *(unsigned*)&v0; vs.y = *(unsigned*)&v1;
            *(uint2*)&Kh[t * 88 + d4 * 4] = ks;
            *(uint2*)&Vh[t * 88 + d4 * 4] = vs;
        }
    }
    if (tid < 240) {                 // zero pad t = 77..79, d = 0..79
        int row = 77 + tid / 80, col = tid % 80;
        Kh[row * 88 + col] = __float2half(0.f);
        Vh[row * 88 + col] = __float2half(0.f);
    }

    // Q fragments: fp32 gmem float2 -> half2 (A-frag: a0=(m=r,k=2q,2q+1) etc.)
    const float* qg = g_q + ((size_t)b * SP + q0 + mb) * INNER + h * HDIM;
    unsigned qf[5][4];
#pragma unroll
    for (int k8 = 0; k8 < 5; k8++) {
        int c = k8 * 16 + q2;
        float2 v0 = *(const float2*)(qg + (size_t)r * INNER + c);
        float2 v1 = *(const float2*)(qg + (size_t)(r + 8) * INNER + c);
        float2 v2 = *(const float2*)(qg + (size_t)r * INNER + c + 8);
        float2 v3 = *(const float2*)(qg + (size_t)(r + 8) * INNER + c + 8);
        __half2 h0 = __floats2half2_rn(v0.x, v0.y);
        __half2 h1 = __floats2half2_rn(v1.x, v1.y);
        __half2 h2 = __floats2half2_rn(v2.x, v2.y);
        __half2 h3 = __floats2half2_rn(v3.x, v3.y);
        qf[k8][0] = *(unsigned*)&h0;
        qf[k8][1] = *(unsigned*)&h1;
        qf[k8][2] = *(unsigned*)&h2;
        qf[k8][3] = *(unsigned*)&h3;
    }
    __syncthreads();

    // ---- S = Q K^T ----  (B-frags: ldsm4 on Kh, rows=t, cols=d)
    uint32_t kBase = sb + (uint32_t)(((lane & 7) + ((lane & 16) ? 8 : 0)) * 88
                                     + ((lane & 8) ? 8 : 0)) * 2;
    float acc[10][4];
#pragma unroll
    for (int i = 0; i < 10; i++)
#pragma unroll
        for (int j = 0; j < 4; j++) acc[i][j] = 0.f;

#pragma unroll
    for (int k8 = 0; k8 < 5; k8++) {
#pragma unroll
        for (int tp = 0; tp < 5; tp++) {
            unsigned bb[4];
            ldsm4(bb, kBase + tp * 2816 + k8 * 32);
            mma_f16(acc[2 * tp],     qf[k8][0], qf[k8][1], qf[k8][2], qf[k8][3],
                    bb[0], bb[1]);
            mma_f16(acc[2 * tp + 1], qf[k8][0], qf[k8][1], qf[k8][2], qf[k8][3],
                    bb[2], bb[3]);
        }
    }

    // ---- softmax (un-normalized; keep 1/sum per row-half) ----
    const float scale = 0.11180339887498949f;
    float invs[2];
#pragma unroll
    for (int hf = 0; hf < 2; hf++) {
        float mx = -1e30f;
#pragma unroll
        for (int in_ = 0; in_ < 10; in_++) {
            int c0 = in_ * 8 + q2;
            float v0 = (c0     < TT) ? acc[in_][hf * 2]     * scale : -1e30f;
            float v1 = (c0 + 1 < TT) ? acc[in_][hf * 2 + 1] * scale : -1e30f;
            acc[in_][hf * 2] = v0; acc[in_][hf * 2 + 1] = v1;
            mx = fmaxf(mx, fmaxf(v0, v1));
        }
        mx = fmaxf(mx, __shfl_xor_sync(0xffffffffu, mx, 1));
        mx = fmaxf(mx, __shfl_xor_sync(0xffffffffu, mx, 2));
        float s = 0.f;
#pragma unroll
        for (int in_ = 0; in_ < 10; in_++) {
            int c0 = in_ * 8 + q2;
            float e0 = (c0     < TT) ? __expf(acc[in_][hf * 2]     - mx) : 0.f;
            float e1 = (c0 + 1 < TT) ? __expf(acc[in_][hf * 2 + 1] - mx) : 0.f;
            acc[in_][hf * 2] = e0; acc[in_][hf * 2 + 1] = e1;
            s += e0 + e1;
        }
        s += __shfl_xor_sync(0xffffffffu, s, 1);
        s += __shfl_xor_sync(0xffffffffu, s, 2);
        invs[hf] = 1.f / s;
    }

    // ---- P fragments: direct repack of S accumulators ----
    unsigned pf[5][4];
#pragma unroll
    for (int k8 = 0; k8 < 5; k8++) {
        __half2 h0 = __floats2half2_rn(acc[2 * k8][0],     acc[2 * k8][1]);
        __half2 h1 = __floats2half2_rn(acc[2 * k8][2],     acc[2 * k8][3]);
        __half2 h2 = __floats2half2_rn(acc[2 * k8 + 1][0], acc[2 * k8 + 1][1]);
        __half2 h3 = __floats2half2_rn(acc[2 * k8 + 1][2], acc[2 * k8 + 1][3]);
        pf[k8][0] = *(unsigned*)&h0;
        pf[k8][1] = *(unsigned*)&h1;
        pf[k8][2] = *(unsigned*)&h2;
        pf[k8][3] = *(unsigned*)&h3;
    }

    // ---- O = P V ----  (B-frags: ldsm4t on Vh[t][d]; vb pairing (0,2)/(1,3))
    uint32_t vBase = sb + 14080 + (uint32_t)(((lane & 7) + ((lane & 16) ? 8 : 0)) * 88) * 2
                   + (uint32_t)((lane & 8) ? 16 : 0);
    float oc[10][4];
#pragma unroll
    for (int i = 0; i < 10; i++)
#pragma unroll
        for (int j = 0; j < 4; j++) oc[i][j] = 0.f;

#pragma unroll
    for (int k8 = 0; k8 < 5; k8++) {
#pragma unroll
        for (int dp = 0; dp < 5; dp++) {
            unsigned vb[4];
            ldsm4t(vb, vBase + k8 * 2816 + dp * 32);
            mma_f16(oc[2 * dp],     pf[k8][0], pf[k8][1], pf[k8][2], pf[k8][3],
                    vb[0], vb[2]);
            mma_f16(oc[2 * dp + 1], pf[k8][0], pf[k8][1], pf[k8][2], pf[k8][3],
                    vb[1], vb[3]);
        }
    }

    // ---- normalize + write fp16 ----
    __half* og = g_at16 + ((size_t)b * SP + q0 + mb) * INNER + h * HDIM;
#pragma unroll
    for (int in_ = 0; in_ < 10; in_++) {
        int c = in_ * 8 + q2;
        *(__half2*)(og + (size_t)r * INNER + c) =
            __floats2half2_rn(oc[in_][0] * invs[0], oc[in_][1] * invs[0]);
        *(__half2*)(og + (size_t)(r + 8) * INNER + c) =
            __floats2half2_rn(oc[in_][2] * invs[1], oc[in_][3] * invs[1]);
    }
}

// ---------------- launch ----------------
extern "C" void kernel_launch(void* const* d_in, const int* in_sizes, int n_in,
                              void* d_out, int out_size)
{
    (void)in_sizes; (void)n_in; (void)out_size;
    const float* hs  = (const float*)d_in[0];
    const float* enc = (const float*)d_in[1];
    const float* lnw = (const float*)d_in[2];
    const float* lnb = (const float*)d_in[3];
    const float* wq  = (const float*)d_in[4];
    const float* wk  = (const float*)d_in[5];
    const float* wv  = (const float*)d_in[6];
    const float* wo  = (const float*)d_in[7];
    const float* bo  = (const float*)d_in[8];
    float* out = (float*)d_out;

    float *p_q, *p_k, *p_v;
    __half *p_x16, *p_at16, *p_e16, *p_wq16, *p_wk16, *p_wv16, *p_wo16;
    cudaGetSymbolAddress((void**)&p_q,    g_q);
    cudaGetSymbolAddress((void**)&p_k,    g_k);
    cudaGetSymbolAddress((void**)&p_v,    g_v);
    cudaGetSymbolAddress((void**)&p_x16,  g_x16);
    cudaGetSymbolAddress((void**)&p_at16, g_at16);
    cudaGetSymbolAddress((void**)&p_e16,  g_e16);
    cudaGetSymbolAddress((void**)&p_wq16, g_wq16);
    cudaGetSymbolAddress((void**)&p_wk16, g_wk16);
    cudaGetSymbolAddress((void**)&p_wv16, g_wv16);
    cudaGetSymbolAddress((void**)&p_wo16, g_wo16);

    cudaFuncSetAttribute(gemm_h<0, false>,
                         cudaFuncAttributeMaxDynamicSharedMemorySize, HGSMEM);
    cudaFuncSetAttribute(gemm_h<0, true>,
                         cudaFuncAttributeMaxDynamicSharedMemorySize, HGSMEM);
    cudaFuncSetAttribute(gemm_h<1, false>,
                         cudaFuncAttributeMaxDynamicSharedMemorySize, HGSMEM);
    cudaFuncSetAttribute(attn_mma,
                         cudaFuncAttributeMaxDynamicSharedMemorySize, AT_SMEM);

    // one-time fp16 conversions
    cvt_w_t<<<dim3(INNER / 32, CHN / 32), 256>>>(wq, p_wq16, CHN, INNER);
    cvt_w_t<<<dim3(INNER / 32, XDIM / 32), 256>>>(wk, p_wk16, XDIM, INNER);
    cvt_w_t<<<dim3(INNER / 32, XDIM / 32), 256>>>(wv, p_wv16, XDIM, INNER);
    cvt_w_t<<<dim3(CHN / 32, INNER / 32), 256>>>(wo, p_wo16, INNER, CHN);
    {
        int n = BATCH * TT * XDIM;
        cvt16<<<(n + 255) / 256, 256>>>(enc, p_e16, n);
    }

    // LN stats + normalize/transpose to fp16 [b][s][c]
    ln_stats<<<dim3(SP / 256, BATCH), 256>>>(hs);
    ln_t16<<<dim3(SP / 32, CHN / 32, BATCH), 256>>>(hs, lnw, lnb);

    // Q = x16 @ wq16^T (fp32 out)
    gemm_h<0, false><<<dim3(INNER / 128, (BATCH * SP) / 128), 256, HGSMEM>>>(
        p_x16, p_wq16, p_q, BATCH * SP, INNER, CHN, CHN, nullptr, nullptr);

    // K, V = e16 @ w^T   (M = 1232, guarded)
    int mkv = (BATCH * TT + 127) / 128;
    gemm_h<0, true><<<dim3(INNER / 128, mkv), 256, HGSMEM>>>(
        p_e16, p_wk16, p_k, BATCH * TT, INNER, XDIM, XDIM, nullptr, nullptr);
    gemm_h<0, true><<<dim3(INNER / 128, mkv), 256, HGSMEM>>>(
        p_e16, p_wv16, p_v, BATCH * TT, INNER, XDIM, XDIM, nullptr, nullptr);

    // attention (fp16 tensor-core)
    attn_mma<<<dim3(SP / 128, NHE, BATCH), 256, AT_SMEM>>>();

    // out = at16 @ wo16^T + bo + residual (transposed store, fp32)
    gemm_h<1, false><<<dim3(CHN / 128, (BATCH * SP) / 128), 256, HGSMEM>>>(
        p_at16, p_wo16, out, BATCH * SP, CHN, INNER, INNER, bo, hs);
}

// round 13
// speedup vs baseline: 1.0961x; 1.0191x over previous
#include <cuda_runtime.h>
#include <cuda_fp16.h>
#include <math.h>
#include <stdint.h>

#define BATCH 16
#define CHN   640
#define SP    4096
#define TT    77
#define XDIM  768
#define NHE   8
#define HDIM  80
#define INNER 640

// ---------------- scratch ----------------
__device__ __half g_q16 [(size_t)BATCH * SP * INNER];
__device__ __half g_k16 [(size_t)BATCH * TT * INNER];
__device__ __half g_v16 [(size_t)BATCH * TT * INNER];
__device__ __half g_x16 [(size_t)BATCH * SP * CHN];     // LN(hs) [b][s][c]
__device__ __half g_at16[(size_t)BATCH * SP * INNER];   // attn out
__device__ __half g_e16 [(size_t)BATCH * TT * XDIM];
__device__ __half g_wq16[(size_t)INNER * CHN];          // [N][K]
__device__ __half g_wk16[(size_t)INNER * XDIM];
__device__ __half g_wv16[(size_t)INNER * XDIM];
__device__ __half g_wo16[(size_t)CHN * INNER];
__device__ float  g_mu  [(size_t)BATCH * SP];
__device__ float  g_rs  [(size_t)BATCH * SP];

// ---------------- helpers ----------------
__device__ __forceinline__ uint32_t smem_u32(const void* p) {
    uint32_t a;
    asm("{ .reg .u64 t; cvta.to.shared.u64 t, %1; cvt.u32.u64 %0, t; }"
        : "=r"(a) : "l"(p));
    return a;
}
__device__ __forceinline__ void cp16(uint32_t dst, const void* src, bool v) {
    int sz = v ? 16 : 0;
    asm volatile("cp.async.cg.shared.global [%0], [%1], 16, %2;"
                 :: "r"(dst), "l"(src), "r"(sz) : "memory");
}
#define CP_COMMIT() asm volatile("cp.async.commit_group;" ::: "memory")
#define CP_WAIT1()  asm volatile("cp.async.wait_group 1;" ::: "memory")
#define CP_WAIT0()  asm volatile("cp.async.wait_group 0;" ::: "memory")

__device__ __forceinline__ void ldsm4(unsigned r[4], uint32_t a) {
    asm volatile("ldmatrix.sync.aligned.m8n8.x4.shared.b16 {%0,%1,%2,%3}, [%4];"
                 : "=r"(r[0]), "=r"(r[1]), "=r"(r[2]), "=r"(r[3]) : "r"(a));
}
__device__ __forceinline__ void ldsm4t(unsigned r[4], uint32_t a) {
    asm volatile("ldmatrix.sync.aligned.m8n8.x4.trans.shared.b16 {%0,%1,%2,%3}, [%4];"
                 : "=r"(r[0]), "=r"(r[1]), "=r"(r[2]), "=r"(r[3]) : "r"(a));
}

__device__ __forceinline__ void mma_f16(float c[4], unsigned a0, unsigned a1,
                                        unsigned a2, unsigned a3,
                                        unsigned b0, unsigned b1)
{
    asm volatile(
        "mma.sync.aligned.m16n8k16.row.col.f32.f16.f16.f32 "
        "{%0,%1,%2,%3},{%4,%5,%6,%7},{%8,%9},{%0,%1,%2,%3};"
        : "+f"(c[0]), "+f"(c[1]), "+f"(c[2]), "+f"(c[3])
        : "r"(a0), "r"(a1), "r"(a2), "r"(a3), "r"(b0), "r"(b1));
}

// ---------------- LN stats ----------------
__global__ void __launch_bounds__(256) ln_stats(const float* __restrict__ x)
{
    int s = blockIdx.x * 256 + threadIdx.x;
    int b = blockIdx.y;
    const float* xp = x + (size_t)b * CHN * SP + s;
    float sum = 0.f, sumsq = 0.f;
    for (int c = 0; c < CHN; c++) { float v = xp[(size_t)c * SP]; sum += v; sumsq += v * v; }
    float mu = sum * (1.0f / CHN);
    float var = sumsq * (1.0f / CHN) - mu * mu;
    g_mu[(size_t)b * SP + s] = mu;
    g_rs[(size_t)b * SP + s] = rsqrtf(var + 1e-6f);
}

// ---------------- normalize + transpose -> fp16 [b][s][c] ----------------
__global__ void __launch_bounds__(256) ln_t16(const float* __restrict__ x,
                                              const float* __restrict__ lw,
                                              const float* __restrict__ lb)
{
    __shared__ float t[32][33];
    int s0 = blockIdx.x * 32, c0 = blockIdx.y * 32, b = blockIdx.z;
    int xl = threadIdx.x & 31, y = (threadIdx.x >> 5) * 4;
#pragma unroll
    for (int i = 0; i < 4; i++)
        t[y + i][xl] = x[((size_t)b * CHN + c0 + y + i) * SP + s0 + xl];
    __syncthreads();
    float wv = lw[c0 + xl], bv = lb[c0 + xl];
#pragma unroll
    for (int i = 0; i < 4; i++) {
        int s = s0 + y + i;
        float mu = g_mu[(size_t)b * SP + s];
        float rs = g_rs[(size_t)b * SP + s];
        float v = (t[xl][y + i] - mu) * rs * wv + bv;
        g_x16[((size_t)b * SP + s) * CHN + c0 + xl] = __float2half_rn(v);
    }
}

// ---------------- weight transpose+cvt [R][C] fp32 -> [C][R] fp16 ----------------
__global__ void __launch_bounds__(256) cvt_w_t(const float* __restrict__ in,
                                               __half* __restrict__ out, int R, int C)
{
    __shared__ float t[32][33];
    int c0 = blockIdx.x * 32, r0 = blockIdx.y * 32;
    int xl = threadIdx.x & 31, y = (threadIdx.x >> 5) * 4;
#pragma unroll
    for (int i = 0; i < 4; i++)
        t[y + i][xl] = in[(size_t)(r0 + y + i) * C + c0 + xl];
    __syncthreads();
#pragma unroll
    for (int i = 0; i < 4; i++)
        out[(size_t)(c0 + y + i) * R + r0 + xl] = __float2half_rn(t[xl][y + i]);
}

// ---------------- elementwise cvt ----------------
__global__ void __launch_bounds__(256) cvt16(const float* __restrict__ in,
                                             __half* __restrict__ out, int n)
{
    int i = blockIdx.x * 256 + threadIdx.x;
    if (i < n) out[i] = __float2half_rn(in[i]);
}

// ---------------- fp16 mma GEMM: D = A[M][K] * Bt[N][K]^T ----------------
// 3-stage cp.async pipeline; fragments via ldmatrix.x4.
// EPI 0: C[m][n] fp32;  EPI 1: out[b][n][s] fp32 + bias + resid;  EPI 2: C fp16
#define HBOFF  10240
#define HSTG   20480
#define HGSMEM (3 * HSTG)

template<int EPI, bool MG>
__global__ void __launch_bounds__(256, 2)
gemm_h(const __half* __restrict__ A, const __half* __restrict__ Bt,
       void* __restrict__ CoutV, int M, int N, int K, int lda,
       const float* __restrict__ bias, const float* __restrict__ resid)
{
    extern __shared__ char smc[];
    uint32_t sb = smem_u32(smc);

    int tid = threadIdx.x, lane = tid & 31, w = tid >> 5;
    int r = lane >> 2, q = lane & 3;
    int wm = w & 3, wn = w >> 2;
    int m0 = blockIdx.y * 128;
    int n0 = blockIdx.x * 128;
    int mb = wm * 32, nb = wn * 64;
    int NT = K >> 5;

    uint32_t offA = (uint32_t)((mb + (lane & 15)) * 40 + ((lane & 16) ? 8 : 0)) * 2;
    uint32_t offB = (uint32_t)((nb + (lane & 7) + ((lane & 16) ? 8 : 0)) * 40
                               + ((lane & 8) ? 8 : 0)) * 2;

    float acc[2][8][4];
#pragma unroll
    for (int i = 0; i < 2; i++)
#pragma unroll
        for (int j = 0; j < 8; j++)
#pragma unroll
            for (int l = 0; l < 4; l++) acc[i][j][l] = 0.f;

    auto load_stage = [&](int slot, int k0) {
        uint32_t st = sb + slot * HSTG;
#pragma unroll
        for (int i = 0; i < 2; i++) {
            int cid = tid + i * 256;
            int row = cid >> 2, ch = cid & 3;
            bool v = !MG || (m0 + row) < M;
            cp16(st + row * 80 + ch * 16,
                 A + (size_t)(m0 + row) * lda + k0 + ch * 8, v);
        }
#pragma unroll
        for (int i = 0; i < 2; i++) {
            int cid = tid + i * 256;
            int row = cid >> 2, ch = cid & 3;
            cp16(st + HBOFF + row * 80 + ch * 16,
                 Bt + (size_t)(n0 + row) * K + k0 + ch * 8, true);
        }
    };

    load_stage(0, 0);  CP_COMMIT();
    load_stage(1, 32); CP_COMMIT();

    for (int t = 0; t < NT; t++) {
        if (t == NT - 1) CP_WAIT0(); else CP_WAIT1();
        __syncthreads();
        if (t + 2 < NT) { load_stage((t + 2) % 3, (t + 2) * 32); CP_COMMIT(); }

        int slot = t % 3;
        uint32_t aBase = sb + slot * HSTG + offA;
        uint32_t bBase = sb + slot * HSTG + HBOFF + offB;

        unsigned ac[2][4], an[2][4];
        ldsm4(ac[0], aBase);
        ldsm4(ac[1], aBase + 1280);
#pragma unroll
        for (int kc = 0; kc < 2; kc++) {
            if (kc == 0) {
                ldsm4(an[0], aBase + 32);
                ldsm4(an[1], aBase + 1280 + 32);
            }
            unsigned bb[4][4];
#pragma unroll
            for (int j = 0; j < 4; j++)
                ldsm4(bb[j], bBase + j * 1280 + kc * 32);
#pragma unroll
            for (int j = 0; j < 4; j++) {
#pragma unroll
                for (int im = 0; im < 2; im++)
                    mma_f16(acc[im][2 * j], ac[im][0], ac[im][1], ac[im][2],
                            ac[im][3], bb[j][0], bb[j][1]);
#pragma unroll
                for (int im = 0; im < 2; im++)
                    mma_f16(acc[im][2 * j + 1], ac[im][0], ac[im][1], ac[im][2],
                            ac[im][3], bb[j][2], bb[j][3]);
            }
            if (kc == 0) {
#pragma unroll
                for (int im = 0; im < 2; im++)
#pragma unroll
                    for (int jj = 0; jj < 4; jj++) ac[im][jj] = an[im][jj];
            }
        }
    }
    __syncthreads();

    // -------- epilogue --------
    float* Cs = (float*)smc;
    if (EPI != 1) {
#pragma unroll 1
        for (int ch = 0; ch < 4; ch++) {
            __syncthreads();
            if (wm == ch) {
#pragma unroll
                for (int im = 0; im < 2; im++) {
                    int r0 = im * 16 + r;
#pragma unroll
                    for (int in_ = 0; in_ < 8; in_++) {
                        int cc = nb + in_ * 8 + q * 2;
                        Cs[r0 * 132 + cc]           = acc[im][in_][0];
                        Cs[r0 * 132 + cc + 1]       = acc[im][in_][1];
                        Cs[(r0 + 8) * 132 + cc]     = acc[im][in_][2];
                        Cs[(r0 + 8) * 132 + cc + 1] = acc[im][in_][3];
                    }
                }
            }
            __syncthreads();
            for (int t = tid; t < 32 * 128; t += 256) {
                int ml = t >> 7, n = t & 127;
                int m = m0 + ch * 32 + ml;
                if (MG && m >= M) continue;
                if (EPI == 0)
                    ((float*)CoutV)[(size_t)m * N + n0 + n] = Cs[ml * 132 + n];
                else
                    ((__half*)CoutV)[(size_t)m * N + n0 + n] =
                        __float2half_rn(Cs[ml * 132 + n]);
            }
        }
    } else {
#pragma unroll 1
        for (int ch = 0; ch < 4; ch++) {
            __syncthreads();
            if (wn == (ch >> 1)) {
                int inlo = (ch & 1) * 4;
#pragma unroll
                for (int im = 0; im < 2; im++) {
                    int mrow = mb + im * 16 + r;
#pragma unroll
                    for (int ii = 0; ii < 4; ii++) {
                        int in_ = inlo + ii;
                        int nl = in_ * 8 + q * 2 - (ch & 1) * 32;
                        Cs[nl * 132 + mrow]           = acc[im][in_][0];
                        Cs[(nl + 1) * 132 + mrow]     = acc[im][in_][1];
                        Cs[nl * 132 + mrow + 8]       = acc[im][in_][2];
                        Cs[(nl + 1) * 132 + mrow + 8] = acc[im][in_][3];
                    }
                }
            }
            __syncthreads();
            for (int t = tid; t < 32 * 128; t += 256) {
                int nl = t >> 7, ml = t & 127;
                int n = n0 + ch * 32 + nl;
                int m = m0 + ml;
                int b = m >> 12, s = m & (SP - 1);
                size_t addr = (size_t)b * CHN * SP + (size_t)n * SP + s;
                ((float*)CoutV)[addr] = Cs[nl * 132 + ml] + bias[n] + resid[addr];
            }
        }
    }
}

// ---------------- fp16 tensor-core attention ----------------
// K,V staged fp16 [t][d] (pitch 88h) straight via cp.async. Q frags = direct
// 4B loads of packed half2. QK B-frags: ldsm4 on K; PV B-frags: ldsm4t on V.
#define AT_SMEM 28160

__global__ void __launch_bounds__(256, 2) attn_mma()
{
    extern __shared__ __half smh[];
    __half* Kh = smh;            // [80][88]
    __half* Vh = smh + 7040;     // [80][88]

    int tid = threadIdx.x, lane = tid & 31, w = tid >> 5;
    int b = blockIdx.z, h = blockIdx.y;
    int q0 = blockIdx.x * 128;
    int mb = w * 16;
    int r = lane >> 2, q = lane & 3, q2 = q * 2;
    uint32_t sb = smem_u32(smh);

    const __half* kg = g_k16 + (size_t)b * TT * INNER + h * HDIM;
    const __half* vg = g_v16 + (size_t)b * TT * INNER + h * HDIM;

    // stage K,V via cp.async: 77 rows x 10 16B-chunks each
#pragma unroll
    for (int i = 0; i < 4; i++) {
        int cid = tid + i * 256;
        if (cid < 770) {
            int t = cid / 10, ch = cid % 10;
            cp16(sb + (t * 88 + ch * 8) * 2, kg + (size_t)t * INNER + ch * 8, true);
            cp16(sb + (7040 + t * 88 + ch * 8) * 2, vg + (size_t)t * INNER + ch * 8, true);
        }
    }
    CP_COMMIT();

    // zero pads t = 77..79 (distinct region from staging)
    if (tid < 240) {
        int row = 77 + tid / 80, col = tid % 80;
        Kh[row * 88 + col] = __float2half(0.f);
        Vh[row * 88 + col] = __float2half(0.f);
    }

    // Q fragments: direct packed-half2 loads
    const __half* qg = g_q16 + ((size_t)b * SP + q0 + mb) * INNER + h * HDIM;
    unsigned qf[5][4];
#pragma unroll
    for (int k8 = 0; k8 < 5; k8++) {
        int c = k8 * 16 + q2;
        qf[k8][0] = *(const unsigned*)(qg + (size_t)r * INNER + c);
        qf[k8][1] = *(const unsigned*)(qg + (size_t)(r + 8) * INNER + c);
        qf[k8][2] = *(const unsigned*)(qg + (size_t)r * INNER + c + 8);
        qf[k8][3] = *(const unsigned*)(qg + (size_t)(r + 8) * INNER + c + 8);
    }
    CP_WAIT0();
    __syncthreads();

    // ---- S = Q K^T ----
    uint32_t kBase = sb + (uint32_t)(((lane & 7) + ((lane & 16) ? 8 : 0)) * 88
                                     + ((lane & 8) ? 8 : 0)) * 2;
    float acc[10][4];
#pragma unroll
    for (int i = 0; i < 10; i++)
#pragma unroll
        for (int j = 0; j < 4; j++) acc[i][j] = 0.f;

#pragma unroll
    for (int k8 = 0; k8 < 5; k8++) {
#pragma unroll
        for (int tp = 0; tp < 5; tp++) {
            unsigned bb[4];
            ldsm4(bb, kBase + tp * 2816 + k8 * 32);
            mma_f16(acc[2 * tp],     qf[k8][0], qf[k8][1], qf[k8][2], qf[k8][3],
                    bb[0], bb[1]);
            mma_f16(acc[2 * tp + 1], qf[k8][0], qf[k8][1], qf[k8][2], qf[k8][3],
                    bb[2], bb[3]);
        }
    }

    // ---- softmax (un-normalized; keep 1/sum per row-half) ----
    const float scale = 0.11180339887498949f;
    float invs[2];
#pragma unroll
    for (int hf = 0; hf < 2; hf++) {
        float mx = -1e30f;
#pragma unroll
        for (int in_ = 0; in_ < 10; in_++) {
            int c0 = in_ * 8 + q2;
            float v0 = (c0     < TT) ? acc[in_][hf * 2]     * scale : -1e30f;
            float v1 = (c0 + 1 < TT) ? acc[in_][hf * 2 + 1] * scale : -1e30f;
            acc[in_][hf * 2] = v0; acc[in_][hf * 2 + 1] = v1;
            mx = fmaxf(mx, fmaxf(v0, v1));
        }
        mx = fmaxf(mx, __shfl_xor_sync(0xffffffffu, mx, 1));
        mx = fmaxf(mx, __shfl_xor_sync(0xffffffffu, mx, 2));
        float s = 0.f;
#pragma unroll
        for (int in_ = 0; in_ < 10; in_++) {
            int c0 = in_ * 8 + q2;
            float e0 = (c0     < TT) ? __expf(acc[in_][hf * 2]     - mx) : 0.f;
            float e1 = (c0 + 1 < TT) ? __expf(acc[in_][hf * 2 + 1] - mx) : 0.f;
            acc[in_][hf * 2] = e0; acc[in_][hf * 2 + 1] = e1;
            s += e0 + e1;
        }
        s += __shfl_xor_sync(0xffffffffu, s, 1);
        s += __shfl_xor_sync(0xffffffffu, s, 2);
        invs[hf] = 1.f / s;
    }

    // ---- P fragments: direct repack of S accumulators ----
    unsigned pf[5][4];
#pragma unroll
    for (int k8 = 0; k8 < 5; k8++) {
        __half2 h0 = __floats2half2_rn(acc[2 * k8][0],     acc[2 * k8][1]);
        __half2 h1 = __floats2half2_rn(acc[2 * k8][2],     acc[2 * k8][3]);
        __half2 h2 = __floats2half2_rn(acc[2 * k8 + 1][0], acc[2 * k8 + 1][1]);
        __half2 h3 = __floats2half2_rn(acc[2 * k8 + 1][2], acc[2 * k8 + 1][3]);
        pf[k8][0] = *(unsigned*)&h0;
        pf[k8][1] = *(unsigned*)&h1;
        pf[k8][2] = *(unsigned*)&h2;
        pf[k8][3] = *(unsigned*)&h3;
    }

    // ---- O = P V ----  (B-frags: ldsm4t on Vh[t][d]; vb pairing (0,2)/(1,3))
    uint32_t vBase = sb + 14080 + (uint32_t)(((lane & 7) + ((lane & 16) ? 8 : 0)) * 88) * 2
                   + (uint32_t)((lane & 8) ? 16 : 0);
    float oc[10][4];
#pragma unroll
    for (int i = 0; i < 10; i++)
#pragma unroll
        for (int j = 0; j < 4; j++) oc[i][j] = 0.f;

#pragma unroll
    for (int k8 = 0; k8 < 5; k8++) {
#pragma unroll
        for (int dp = 0; dp < 5; dp++) {
            unsigned vb[4];
            ldsm4t(vb, vBase + k8 * 2816 + dp * 32);
            mma_f16(oc[2 * dp],     pf[k8][0], pf[k8][1], pf[k8][2], pf[k8][3],
                    vb[0], vb[2]);
            mma_f16(oc[2 * dp + 1], pf[k8][0], pf[k8][1], pf[k8][2], pf[k8][3],
                    vb[1], vb[3]);
        }
    }

    // ---- normalize + write fp16 ----
    __half* og = g_at16 + ((size_t)b * SP + q0 + mb) * INNER + h * HDIM;
#pragma unroll
    for (int in_ = 0; in_ < 10; in_++) {
        int c = in_ * 8 + q2;
        *(__half2*)(og + (size_t)r * INNER + c) =
            __floats2half2_rn(oc[in_][0] * invs[0], oc[in_][1] * invs[0]);
        *(__half2*)(og + (size_t)(r + 8) * INNER + c) =
            __floats2half2_rn(oc[in_][2] * invs[1], oc[in_][3] * invs[1]);
    }
}

// ---------------- launch ----------------
extern "C" void kernel_launch(void* const* d_in, const int* in_sizes, int n_in,
                              void* d_out, int out_size)
{
    (void)in_sizes; (void)n_in; (void)out_size;
    const float* hs  = (const float*)d_in[0];
    const float* enc = (const float*)d_in[1];
    const float* lnw = (const float*)d_in[2];
    const float* lnb = (const float*)d_in[3];
    const float* wq  = (const float*)d_in[4];
    const float* wk  = (const float*)d_in[5];
    const float* wv  = (const float*)d_in[6];
    const float* wo  = (const float*)d_in[7];
    const float* bo  = (const float*)d_in[8];
    float* out = (float*)d_out;

    __half *p_q16, *p_k16, *p_v16, *p_x16, *p_at16, *p_e16;
    __half *p_wq16, *p_wk16, *p_wv16, *p_wo16;
    cudaGetSymbolAddress((void**)&p_q16,  g_q16);
    cudaGetSymbolAddress((void**)&p_k16,  g_k16);
    cudaGetSymbolAddress((void**)&p_v16,  g_v16);
    cudaGetSymbolAddress((void**)&p_x16,  g_x16);
    cudaGetSymbolAddress((void**)&p_at16, g_at16);
    cudaGetSymbolAddress((void**)&p_e16,  g_e16);
    cudaGetSymbolAddress((void**)&p_wq16, g_wq16);
    cudaGetSymbolAddress((void**)&p_wk16, g_wk16);
    cudaGetSymbolAddress((void**)&p_wv16, g_wv16);
    cudaGetSymbolAddress((void**)&p_wo16, g_wo16);

    cudaFuncSetAttribute(gemm_h<2, false>,
                         cudaFuncAttributeMaxDynamicSharedMemorySize, HGSMEM);
    cudaFuncSetAttribute(gemm_h<2, true>,
                         cudaFuncAttributeMaxDynamicSharedMemorySize, HGSMEM);
    cudaFuncSetAttribute(gemm_h<1, false>,
                         cudaFuncAttributeMaxDynamicSharedMemorySize, HGSMEM);
    cudaFuncSetAttribute(attn_mma,
                         cudaFuncAttributeMaxDynamicSharedMemorySize, AT_SMEM);

    // one-time fp16 conversions
    cvt_w_t<<<dim3(INNER / 32, CHN / 32), 256>>>(wq, p_wq16, CHN, INNER);
    cvt_w_t<<<dim3(INNER / 32, XDIM / 32), 256>>>(wk, p_wk16, XDIM, INNER);
    cvt_w_t<<<dim3(INNER / 32, XDIM / 32), 256>>>(wv, p_wv16, XDIM, INNER);
    cvt_w_t<<<dim3(CHN / 32, INNER / 32), 256>>>(wo, p_wo16, INNER, CHN);
    {
        int n = BATCH * TT * XDIM;
        cvt16<<<(n + 255) / 256, 256>>>(enc, p_e16, n);
    }

    // LN stats + normalize/transpose to fp16 [b][s][c]
    ln_stats<<<dim3(SP / 256, BATCH), 256>>>(hs);
    ln_t16<<<dim3(SP / 32, CHN / 32, BATCH), 256>>>(hs, lnw, lnb);

    // Q = x16 @ wq16^T (fp16 out)
    gemm_h<2, false><<<dim3(INNER / 128, (BATCH * SP) / 128), 256, HGSMEM>>>(
        p_x16, p_wq16, p_q16, BATCH * SP, INNER, CHN, CHN, nullptr, nullptr);

    // K, V = e16 @ w^T  (fp16 out, M = 1232 guarded)
    int mkv = (BATCH * TT + 127) / 128;
    gemm_h<2, true><<<dim3(INNER / 128, mkv), 256, HGSMEM>>>(
        p_e16, p_wk16, p_k16, BATCH * TT, INNER, XDIM, XDIM, nullptr, nullptr);
    gemm_h<2, true><<<dim3(INNER / 128, mkv), 256, HGSMEM>>>(
        p_e16, p_wv16, p_v16, BATCH * TT, INNER, XDIM, XDIM, nullptr, nullptr);

    // attention (fp16 tensor-core)
    attn_mma<<<dim3(SP / 128, NHE, BATCH), 256, AT_SMEM>>>();

    // out = at16 @ wo16^T + bo + residual (transposed store, fp32)
    gemm_h<1, false><<<dim3(CHN / 128, (BATCH * SP) / 128), 256, HGSMEM>>>(
        p_at16, p_wo16, out, BATCH * SP, CHN, INNER, INNER, bo, hs);
}

// round 14
// speedup vs baseline: 1.1272x; 1.0284x over previous
#include <cuda_runtime.h>
#include <cuda_fp16.h>
#include <math.h>
#include <stdint.h>

#define BATCH 16
#define CHN   640
#define SP    4096
#define TT    77
#define XDIM  768
#define NHE   8
#define HDIM  80
#define INNER 640
#define KVW   1280          // fused K|V width

// ---------------- scratch ----------------
__device__ __half g_q16  [(size_t)BATCH * SP * INNER];
__device__ __half g_kv16 [(size_t)BATCH * TT * KVW];    // [m][ K(640) | V(640) ]
__device__ __half g_x16  [(size_t)BATCH * SP * CHN];
__device__ __half g_at16 [(size_t)BATCH * SP * INNER];
__device__ __half g_e16  [(size_t)BATCH * TT * XDIM];
__device__ __half g_wq16 [(size_t)INNER * CHN];
__device__ __half g_wkv16[(size_t)KVW * XDIM];          // rows 0..639 wk^T, 640.. wv^T
__device__ __half g_wo16 [(size_t)CHN * INNER];
__device__ float  g_mu   [(size_t)BATCH * SP];
__device__ float  g_rs   [(size_t)BATCH * SP];

// ---------------- helpers ----------------
__device__ __forceinline__ uint32_t smem_u32(const void* p) {
    uint32_t a;
    asm("{ .reg .u64 t; cvta.to.shared.u64 t, %1; cvt.u32.u64 %0, t; }"
        : "=r"(a) : "l"(p));
    return a;
}
__device__ __forceinline__ void cp16(uint32_t dst, const void* src, bool v) {
    int sz = v ? 16 : 0;
    asm volatile("cp.async.cg.shared.global [%0], [%1], 16, %2;"
                 :: "r"(dst), "l"(src), "r"(sz) : "memory");
}
#define CP_COMMIT() asm volatile("cp.async.commit_group;" ::: "memory")
#define CP_WAIT1()  asm volatile("cp.async.wait_group 1;" ::: "memory")
#define CP_WAIT0()  asm volatile("cp.async.wait_group 0;" ::: "memory")

__device__ __forceinline__ void ldsm4(unsigned r[4], uint32_t a) {
    asm volatile("ldmatrix.sync.aligned.m8n8.x4.shared.b16 {%0,%1,%2,%3}, [%4];"
                 : "=r"(r[0]), "=r"(r[1]), "=r"(r[2]), "=r"(r[3]) : "r"(a));
}
__device__ __forceinline__ void ldsm4t(unsigned r[4], uint32_t a) {
    asm volatile("ldmatrix.sync.aligned.m8n8.x4.trans.shared.b16 {%0,%1,%2,%3}, [%4];"
                 : "=r"(r[0]), "=r"(r[1]), "=r"(r[2]), "=r"(r[3]) : "r"(a));
}

__device__ __forceinline__ void mma_f16(float c[4], unsigned a0, unsigned a1,
                                        unsigned a2, unsigned a3,
                                        unsigned b0, unsigned b1)
{
    asm volatile(
        "mma.sync.aligned.m16n8k16.row.col.f32.f16.f16.f32 "
        "{%0,%1,%2,%3},{%4,%5,%6,%7},{%8,%9},{%0,%1,%2,%3};"
        : "+f"(c[0]), "+f"(c[1]), "+f"(c[2]), "+f"(c[3])
        : "r"(a0), "r"(a1), "r"(a2), "r"(a3), "r"(b0), "r"(b1));
}

// ---------------- LN stats ----------------
__global__ void __launch_bounds__(256) ln_stats(const float* __restrict__ x)
{
    int s = blockIdx.x * 256 + threadIdx.x;
    int b = blockIdx.y;
    const float* xp = x + (size_t)b * CHN * SP + s;
    float sum = 0.f, sumsq = 0.f;
    for (int c = 0; c < CHN; c++) { float v = xp[(size_t)c * SP]; sum += v; sumsq += v * v; }
    float mu = sum * (1.0f / CHN);
    float var = sumsq * (1.0f / CHN) - mu * mu;
    g_mu[(size_t)b * SP + s] = mu;
    g_rs[(size_t)b * SP + s] = rsqrtf(var + 1e-6f);
}

// ---------------- normalize + transpose -> fp16 [b][s][c] ----------------
__global__ void __launch_bounds__(256) ln_t16(const float* __restrict__ x,
                                              const float* __restrict__ lw,
                                              const float* __restrict__ lb)
{
    __shared__ float t[32][33];
    int s0 = blockIdx.x * 32, c0 = blockIdx.y * 32, b = blockIdx.z;
    int xl = threadIdx.x & 31, y = (threadIdx.x >> 5) * 4;
#pragma unroll
    for (int i = 0; i < 4; i++)
        t[y + i][xl] = x[((size_t)b * CHN + c0 + y + i) * SP + s0 + xl];
    __syncthreads();
    float wv = lw[c0 + xl], bv = lb[c0 + xl];
#pragma unroll
    for (int i = 0; i < 4; i++) {
        int s = s0 + y + i;
        float mu = g_mu[(size_t)b * SP + s];
        float rs = g_rs[(size_t)b * SP + s];
        float v = (t[xl][y + i] - mu) * rs * wv + bv;
        g_x16[((size_t)b * SP + s) * CHN + c0 + xl] = __float2half_rn(v);
    }
}

// ---------------- weight transpose+cvt [R][C] fp32 -> [C][R] fp16 ----------------
__global__ void __launch_bounds__(256) cvt_w_t(const float* __restrict__ in,
                                               __half* __restrict__ out, int R, int C)
{
    __shared__ float t[32][33];
    int c0 = blockIdx.x * 32, r0 = blockIdx.y * 32;
    int xl = threadIdx.x & 31, y = (threadIdx.x >> 5) * 4;
#pragma unroll
    for (int i = 0; i < 4; i++)
        t[y + i][xl] = in[(size_t)(r0 + y + i) * C + c0 + xl];
    __syncthreads();
#pragma unroll
    for (int i = 0; i < 4; i++)
        out[(size_t)(c0 + y + i) * R + r0 + xl] = __float2half_rn(t[xl][y + i]);
}

// ---------------- elementwise cvt ----------------
__global__ void __launch_bounds__(256) cvt16(const float* __restrict__ in,
                                             __half* __restrict__ out, int n)
{
    int i = blockIdx.x * 256 + threadIdx.x;
    if (i < n) out[i] = __float2half_rn(in[i]);
}

// ---------------- fp16 mma GEMM: D = A[M][K] * Bt[N][K]^T ----------------
// EPI 0: C[m][n] fp32;  EPI 1: out[b][n][s] fp32 + bias + resid;  EPI 2: C fp16
#define HBOFF  10240
#define HSTG   20480
#define HGSMEM (3 * HSTG)

template<int EPI, bool MG>
__global__ void __launch_bounds__(256, 2)
gemm_h(const __half* __restrict__ A, const __half* __restrict__ Bt,
       void* __restrict__ CoutV, int M, int N, int K, int lda,
       const float* __restrict__ bias, const float* __restrict__ resid)
{
    extern __shared__ char smc[];
    uint32_t sb = smem_u32(smc);

    int tid = threadIdx.x, lane = tid & 31, w = tid >> 5;
    int r = lane >> 2, q = lane & 3;
    int wm = w & 3, wn = w >> 2;
    int m0 = blockIdx.y * 128;
    int n0 = blockIdx.x * 128;
    int mb = wm * 32, nb = wn * 64;
    int NT = K >> 5;

    uint32_t offA = (uint32_t)((mb + (lane & 15)) * 40 + ((lane & 16) ? 8 : 0)) * 2;
    uint32_t offB = (uint32_t)((nb + (lane & 7) + ((lane & 16) ? 8 : 0)) * 40
                               + ((lane & 8) ? 8 : 0)) * 2;

    float acc[2][8][4];
#pragma unroll
    for (int i = 0; i < 2; i++)
#pragma unroll
        for (int j = 0; j < 8; j++)
#pragma unroll
            for (int l = 0; l < 4; l++) acc[i][j][l] = 0.f;

    auto load_stage = [&](int slot, int k0) {
        uint32_t st = sb + slot * HSTG;
#pragma unroll
        for (int i = 0; i < 2; i++) {
            int cid = tid + i * 256;
            int row = cid >> 2, ch = cid & 3;
            bool v = !MG || (m0 + row) < M;
            cp16(st + row * 80 + ch * 16,
                 A + (size_t)(m0 + row) * lda + k0 + ch * 8, v);
        }
#pragma unroll
        for (int i = 0; i < 2; i++) {
            int cid = tid + i * 256;
            int row = cid >> 2, ch = cid & 3;
            cp16(st + HBOFF + row * 80 + ch * 16,
                 Bt + (size_t)(n0 + row) * K + k0 + ch * 8, true);
        }
    };

    load_stage(0, 0);  CP_COMMIT();
    load_stage(1, 32); CP_COMMIT();

    for (int t = 0; t < NT; t++) {
        if (t == NT - 1) CP_WAIT0(); else CP_WAIT1();
        __syncthreads();
        if (t + 2 < NT) { load_stage((t + 2) % 3, (t + 2) * 32); CP_COMMIT(); }

        int slot = t % 3;
        uint32_t aBase = sb + slot * HSTG + offA;
        uint32_t bBase = sb + slot * HSTG + HBOFF + offB;

        unsigned ac[2][4], an[2][4];
        ldsm4(ac[0], aBase);
        ldsm4(ac[1], aBase + 1280);
#pragma unroll
        for (int kc = 0; kc < 2; kc++) {
            if (kc == 0) {
                ldsm4(an[0], aBase + 32);
                ldsm4(an[1], aBase + 1280 + 32);
            }
            unsigned bb[4][4];
#pragma unroll
            for (int j = 0; j < 4; j++)
                ldsm4(bb[j], bBase + j * 1280 + kc * 32);
#pragma unroll
            for (int j = 0; j < 4; j++) {
#pragma unroll
                for (int im = 0; im < 2; im++)
                    mma_f16(acc[im][2 * j], ac[im][0], ac[im][1], ac[im][2],
                            ac[im][3], bb[j][0], bb[j][1]);
#pragma unroll
                for (int im = 0; im < 2; im++)
                    mma_f16(acc[im][2 * j + 1], ac[im][0], ac[im][1], ac[im][2],
                            ac[im][3], bb[j][2], bb[j][3]);
            }
            if (kc == 0) {
#pragma unroll
                for (int im = 0; im < 2; im++)
#pragma unroll
                    for (int jj = 0; jj < 4; jj++) ac[im][jj] = an[im][jj];
            }
        }
    }
    __syncthreads();

    // -------- epilogue --------
    float* Cs = (float*)smc;
    if (EPI != 1) {
#pragma unroll 1
        for (int ch = 0; ch < 4; ch++) {
            __syncthreads();
            if (wm == ch) {
#pragma unroll
                for (int im = 0; im < 2; im++) {
                    int r0 = im * 16 + r;
#pragma unroll
                    for (int in_ = 0; in_ < 8; in_++) {
                        int cc = nb + in_ * 8 + q * 2;
                        Cs[r0 * 132 + cc]           = acc[im][in_][0];
                        Cs[r0 * 132 + cc + 1]       = acc[im][in_][1];
                        Cs[(r0 + 8) * 132 + cc]     = acc[im][in_][2];
                        Cs[(r0 + 8) * 132 + cc + 1] = acc[im][in_][3];
                    }
                }
            }
            __syncthreads();
            for (int t = tid; t < 32 * 128; t += 256) {
                int ml = t >> 7, n = t & 127;
                int m = m0 + ch * 32 + ml;
                if (MG && m >= M) continue;
                if (EPI == 0)
                    ((float*)CoutV)[(size_t)m * N + n0 + n] = Cs[ml * 132 + n];
                else
                    ((__half*)CoutV)[(size_t)m * N + n0 + n] =
                        __float2half_rn(Cs[ml * 132 + n]);
            }
        }
    } else {
#pragma unroll 1
        for (int ch = 0; ch < 4; ch++) {
            __syncthreads();
            if (wn == (ch >> 1)) {
                int inlo = (ch & 1) * 4;
#pragma unroll
                for (int im = 0; im < 2; im++) {
                    int mrow = mb + im * 16 + r;
#pragma unroll
                    for (int ii = 0; ii < 4; ii++) {
                        int in_ = inlo + ii;
                        int nl = in_ * 8 + q * 2 - (ch & 1) * 32;
                        Cs[nl * 132 + mrow]           = acc[im][in_][0];
                        Cs[(nl + 1) * 132 + mrow]     = acc[im][in_][1];
                        Cs[nl * 132 + mrow + 8]       = acc[im][in_][2];
                        Cs[(nl + 1) * 132 + mrow + 8] = acc[im][in_][3];
                    }
                }
            }
            __syncthreads();
            for (int t = tid; t < 32 * 128; t += 256) {
                int nl = t >> 7, ml = t & 127;
                int n = n0 + ch * 32 + nl;
                int m = m0 + ml;
                int b = m >> 12, s = m & (SP - 1);
                size_t addr = (size_t)b * CHN * SP + (size_t)n * SP + s;
                ((float*)CoutV)[addr] = Cs[nl * 132 + ml] + bias[n] + resid[addr];
            }
        }
    }
}

// ---------------- fp16 tensor-core attention ----------------
// K,V read from fused g_kv16 [m][1280]. Staged fp16 [t][d] (pitch 88h).
#define AT_SMEM 28160

__global__ void __launch_bounds__(256, 2) attn_mma()
{
    extern __shared__ __half smh[];
    __half* Kh = smh;            // [80][88]
    __half* Vh = smh + 7040;     // [80][88]

    int tid = threadIdx.x, lane = tid & 31, w = tid >> 5;
    int b = blockIdx.z, h = blockIdx.y;
    int q0 = blockIdx.x * 128;
    int mb = w * 16;
    int r = lane >> 2, q = lane & 3, q2 = q * 2;
    uint32_t sb = smem_u32(smh);

    const __half* kg = g_kv16 + (size_t)b * TT * KVW + h * HDIM;
    const __half* vg = kg + INNER;

    // stage K,V via cp.async: 77 rows x 10 16B-chunks each
#pragma unroll
    for (int i = 0; i < 4; i++) {
        int cid = tid + i * 256;
        if (cid < 770) {
            int t = cid / 10, ch = cid % 10;
            cp16(sb + (t * 88 + ch * 8) * 2, kg + (size_t)t * KVW + ch * 8, true);
            cp16(sb + (7040 + t * 88 + ch * 8) * 2, vg + (size_t)t * KVW + ch * 8, true);
        }
    }
    CP_COMMIT();

    if (tid < 240) {                 // zero pads t = 77..79
        int row = 77 + tid / 80, col = tid % 80;
        Kh[row * 88 + col] = __float2half(0.f);
        Vh[row * 88 + col] = __float2half(0.f);
    }

    // Q fragments: direct packed-half2 loads
    const __half* qg = g_q16 + ((size_t)b * SP + q0 + mb) * INNER + h * HDIM;
    unsigned qf[5][4];
#pragma unroll
    for (int k8 = 0; k8 < 5; k8++) {
        int c = k8 * 16 + q2;
        qf[k8][0] = *(const unsigned*)(qg + (size_t)r * INNER + c);
        qf[k8][1] = *(const unsigned*)(qg + (size_t)(r + 8) * INNER + c);
        qf[k8][2] = *(const unsigned*)(qg + (size_t)r * INNER + c + 8);
        qf[k8][3] = *(const unsigned*)(qg + (size_t)(r + 8) * INNER + c + 8);
    }
    CP_WAIT0();
    __syncthreads();

    // ---- S = Q K^T ----
    uint32_t kBase = sb + (uint32_t)(((lane & 7) + ((lane & 16) ? 8 : 0)) * 88
                                     + ((lane & 8) ? 8 : 0)) * 2;
    float acc[10][4];
#pragma unroll
    for (int i = 0; i < 10; i++)
#pragma unroll
        for (int j = 0; j < 4; j++) acc[i][j] = 0.f;

#pragma unroll
    for (int k8 = 0; k8 < 5; k8++) {
#pragma unroll
        for (int tp = 0; tp < 5; tp++) {
            unsigned bb[4];
            ldsm4(bb, kBase + tp * 2816 + k8 * 32);
            mma_f16(acc[2 * tp],     qf[k8][0], qf[k8][1], qf[k8][2], qf[k8][3],
                    bb[0], bb[1]);
            mma_f16(acc[2 * tp + 1], qf[k8][0], qf[k8][1], qf[k8][2], qf[k8][3],
                    bb[2], bb[3]);
        }
    }

    // ---- softmax (un-normalized; keep 1/sum per row-half) ----
    const float scale = 0.11180339887498949f;
    float invs[2];
#pragma unroll
    for (int hf = 0; hf < 2; hf++) {
        float mx = -1e30f;
#pragma unroll
        for (int in_ = 0; in_ < 10; in_++) {
            int c0 = in_ * 8 + q2;
            float v0 = (c0     < TT) ? acc[in_][hf * 2]     * scale : -1e30f;
            float v1 = (c0 + 1 < TT) ? acc[in_][hf * 2 + 1] * scale : -1e30f;
            acc[in_][hf * 2] = v0; acc[in_][hf * 2 + 1] = v1;
            mx = fmaxf(mx, fmaxf(v0, v1));
        }
        mx = fmaxf(mx, __shfl_xor_sync(0xffffffffu, mx, 1));
        mx = fmaxf(mx, __shfl_xor_sync(0xffffffffu, mx, 2));
        float s = 0.f;
#pragma unroll
        for (int in_ = 0; in_ < 10; in_++) {
            int c0 = in_ * 8 + q2;
            float e0 = (c0     < TT) ? __expf(acc[in_][hf * 2]     - mx) : 0.f;
            float e1 = (c0 + 1 < TT) ? __expf(acc[in_][hf * 2 + 1] - mx) : 0.f;
            acc[in_][hf * 2] = e0; acc[in_][hf * 2 + 1] = e1;
            s += e0 + e1;
        }
        s += __shfl_xor_sync(0xffffffffu, s, 1);
        s += __shfl_xor_sync(0xffffffffu, s, 2);
        invs[hf] = 1.f / s;
    }

    // ---- P fragments: direct repack of S accumulators ----
    unsigned pf[5][4];
#pragma unroll
    for (int k8 = 0; k8 < 5; k8++) {
        __half2 h0 = __floats2half2_rn(acc[2 * k8][0],     acc[2 * k8][1]);
        __half2 h1 = __floats2half2_rn(acc[2 * k8][2],     acc[2 * k8][3]);
        __half2 h2 = __floats2half2_rn(acc[2 * k8 + 1][0], acc[2 * k8 + 1][1]);
        __half2 h3 = __floats2half2_rn(acc[2 * k8 + 1][2], acc[2 * k8 + 1][3]);
        pf[k8][0] = *(unsigned*)&h0;
        pf[k8][1] = *(unsigned*)&h1;
        pf[k8][2] = *(unsigned*)&h2;
        pf[k8][3] = *(unsigned*)&h3;
    }

    // ---- O = P V ----
    uint32_t vBase = sb + 14080 + (uint32_t)(((lane & 7) + ((lane & 16) ? 8 : 0)) * 88) * 2
                   + (uint32_t)((lane & 8) ? 16 : 0);
    float oc[10][4];
#pragma unroll
    for (int i = 0; i < 10; i++)
#pragma unroll
        for (int j = 0; j < 4; j++) oc[i][j] = 0.f;

#pragma unroll
    for (int k8 = 0; k8 < 5; k8++) {
#pragma unroll
        for (int dp = 0; dp < 5; dp++) {
            unsigned vb[4];
            ldsm4t(vb, vBase + k8 * 2816 + dp * 32);
            mma_f16(oc[2 * dp],     pf[k8][0], pf[k8][1], pf[k8][2], pf[k8][3],
                    vb[0], vb[2]);
            mma_f16(oc[2 * dp + 1], pf[k8][0], pf[k8][1], pf[k8][2], pf[k8][3],
                    vb[1], vb[3]);
        }
    }

    // ---- normalize + write fp16 ----
    __half* og = g_at16 + ((size_t)b * SP + q0 + mb) * INNER + h * HDIM;
#pragma unroll
    for (int in_ = 0; in_ < 10; in_++) {
        int c = in_ * 8 + q2;
        *(__half2*)(og + (size_t)r * INNER + c) =
            __floats2half2_rn(oc[in_][0] * invs[0], oc[in_][1] * invs[0]);
        *(__half2*)(og + (size_t)(r + 8) * INNER + c) =
            __floats2half2_rn(oc[in_][2] * invs[1], oc[in_][3] * invs[1]);
    }
}

// ---------------- launch ----------------
extern "C" void kernel_launch(void* const* d_in, const int* in_sizes, int n_in,
                              void* d_out, int out_size)
{
    (void)in_sizes; (void)n_in; (void)out_size;
    const float* hs  = (const float*)d_in[0];
    const float* enc = (const float*)d_in[1];
    const float* lnw = (const float*)d_in[2];
    const float* lnb = (const float*)d_in[3];
    const float* wq  = (const float*)d_in[4];
    const float* wk  = (const float*)d_in[5];
    const float* wv  = (const float*)d_in[6];
    const float* wo  = (const float*)d_in[7];
    const float* bo  = (const float*)d_in[8];
    float* out = (float*)d_out;

    __half *p_q16, *p_kv16, *p_x16, *p_at16, *p_e16;
    __half *p_wq16, *p_wkv16, *p_wo16;
    cudaGetSymbolAddress((void**)&p_q16,   g_q16);
    cudaGetSymbolAddress((void**)&p_kv16,  g_kv16);
    cudaGetSymbolAddress((void**)&p_x16,   g_x16);
    cudaGetSymbolAddress((void**)&p_at16,  g_at16);
    cudaGetSymbolAddress((void**)&p_e16,   g_e16);
    cudaGetSymbolAddress((void**)&p_wq16,  g_wq16);
    cudaGetSymbolAddress((void**)&p_wkv16, g_wkv16);
    cudaGetSymbolAddress((void**)&p_wo16,  g_wo16);

    static cudaStream_t s1 = nullptr;
    static cudaEvent_t evF = nullptr, evJ = nullptr;
    if (s1 == nullptr) {
        cudaStreamCreateWithFlags(&s1, cudaStreamNonBlocking);
        cudaEventCreateWithFlags(&evF, cudaEventDisableTiming);
        cudaEventCreateWithFlags(&evJ, cudaEventDisableTiming);
        cudaFuncSetAttribute(gemm_h<2, false>,
                             cudaFuncAttributeMaxDynamicSharedMemorySize, HGSMEM);
        cudaFuncSetAttribute(gemm_h<2, true>,
                             cudaFuncAttributeMaxDynamicSharedMemorySize, HGSMEM);
        cudaFuncSetAttribute(gemm_h<1, false>,
                             cudaFuncAttributeMaxDynamicSharedMemorySize, HGSMEM);
        cudaFuncSetAttribute(attn_mma,
                             cudaFuncAttributeMaxDynamicSharedMemorySize, AT_SMEM);
    }

    // fork: stream B handles the enc -> KV chain
    cudaEventRecord(evF, 0);
    cudaStreamWaitEvent(s1, evF, 0);

    // --- stream B: wk/wv cvt -> enc cvt -> fused KV GEMM ---
    cvt_w_t<<<dim3(INNER / 32, XDIM / 32), 256, 0, s1>>>(wk, p_wkv16, XDIM, INNER);
    cvt_w_t<<<dim3(INNER / 32, XDIM / 32), 256, 0, s1>>>(
        wv, p_wkv16 + (size_t)INNER * XDIM, XDIM, INNER);
    {
        int n = BATCH * TT * XDIM;
        cvt16<<<(n + 255) / 256, 256, 0, s1>>>(enc, p_e16, n);
    }
    gemm_h<2, true><<<dim3(KVW / 128, (BATCH * TT + 127) / 128), 256, HGSMEM, s1>>>(
        p_e16, p_wkv16, p_kv16, BATCH * TT, KVW, XDIM, XDIM, nullptr, nullptr);
    cudaEventRecord(evJ, s1);

    // --- stream A (default): wq/wo cvt -> LN -> Q GEMM ---
    cvt_w_t<<<dim3(INNER / 32, CHN / 32), 256>>>(wq, p_wq16, CHN, INNER);
    cvt_w_t<<<dim3(CHN / 32, INNER / 32), 256>>>(wo, p_wo16, INNER, CHN);
    ln_stats<<<dim3(SP / 256, BATCH), 256>>>(hs);
    ln_t16<<<dim3(SP / 32, CHN / 32, BATCH), 256>>>(hs, lnw, lnb);
    gemm_h<2, false><<<dim3(INNER / 128, (BATCH * SP) / 128), 256, HGSMEM>>>(
        p_x16, p_wq16, p_q16, BATCH * SP, INNER, CHN, CHN, nullptr, nullptr);

    // join
    cudaStreamWaitEvent(0, evJ, 0);

    // attention (fp16 tensor-core)
    attn_mma<<<dim3(SP / 128, NHE, BATCH), 256, AT_SMEM>>>();

    // out = at16 @ wo16^T + bo + residual (transposed store, fp32)
    gemm_h<1, false><<<dim3(CHN / 128, (BATCH * SP) / 128), 256, HGSMEM>>>(
        p_at16, p_wo16, out, BATCH * SP, CHN, INNER, INNER, bo, hs);
}

// round 15
// speedup vs baseline: 1.1583x; 1.0276x over previous
#include <cuda_runtime.h>
#include <cuda_fp16.h>
#include <math.h>
#include <stdint.h>

#define BATCH 16
#define CHN   640
#define SP    4096
#define TT    77
#define XDIM  768
#define NHE   8
#define HDIM  80
#define INNER 640
#define KVW   1280          // fused K|V width

// ---------------- scratch ----------------
__device__ __half g_q16  [(size_t)BATCH * SP * INNER];
__device__ __half g_kv16 [(size_t)BATCH * TT * KVW];    // [m][ K(640) | V(640) ]
__device__ __half g_x16  [(size_t)BATCH * SP * CHN];
__device__ __half g_at16 [(size_t)BATCH * SP * INNER];
__device__ __half g_e16  [(size_t)BATCH * TT * XDIM];
__device__ __half g_wq16 [(size_t)INNER * CHN];
__device__ __half g_wkv16[(size_t)KVW * XDIM];
__device__ __half g_wo16 [(size_t)CHN * INNER];

// ---------------- helpers ----------------
__device__ __forceinline__ uint32_t smem_u32(const void* p) {
    uint32_t a;
    asm("{ .reg .u64 t; cvta.to.shared.u64 t, %1; cvt.u32.u64 %0, t; }"
        : "=r"(a) : "l"(p));
    return a;
}
__device__ __forceinline__ void cp16(uint32_t dst, const void* src, bool v) {
    int sz = v ? 16 : 0;
    asm volatile("cp.async.cg.shared.global [%0], [%1], 16, %2;"
                 :: "r"(dst), "l"(src), "r"(sz) : "memory");
}
#define CP_COMMIT() asm volatile("cp.async.commit_group;" ::: "memory")
#define CP_WAIT1()  asm volatile("cp.async.wait_group 1;" ::: "memory")
#define CP_WAIT0()  asm volatile("cp.async.wait_group 0;" ::: "memory")

__device__ __forceinline__ void ldsm4(unsigned r[4], uint32_t a) {
    asm volatile("ldmatrix.sync.aligned.m8n8.x4.shared.b16 {%0,%1,%2,%3}, [%4];"
                 : "=r"(r[0]), "=r"(r[1]), "=r"(r[2]), "=r"(r[3]) : "r"(a));
}
__device__ __forceinline__ void ldsm4t(unsigned r[4], uint32_t a) {
    asm volatile("ldmatrix.sync.aligned.m8n8.x4.trans.shared.b16 {%0,%1,%2,%3}, [%4];"
                 : "=r"(r[0]), "=r"(r[1]), "=r"(r[2]), "=r"(r[3]) : "r"(a));
}

__device__ __forceinline__ void mma_f16(float c[4], unsigned a0, unsigned a1,
                                        unsigned a2, unsigned a3,
                                        unsigned b0, unsigned b1)
{
    asm volatile(
        "mma.sync.aligned.m16n8k16.row.col.f32.f16.f16.f32 "
        "{%0,%1,%2,%3},{%4,%5,%6,%7},{%8,%9},{%0,%1,%2,%3};"
        : "+f"(c[0]), "+f"(c[1]), "+f"(c[2]), "+f"(c[3])
        : "r"(a0), "r"(a1), "r"(a2), "r"(a3), "r"(b0), "r"(b1));
}

// ---------------- fused LN: stats + normalize + transpose in one pass ----------------
// One CTA per (b, 32 s). Tile [640 c][33 pad] fp32 in smem, stats in-block,
// write fp16 [s][c] half2-coalesced.
#define LN_TILE  (CHN * 33)                       // 21120 floats
#define LN_SMEM  ((LN_TILE + 2 * 8 * 33 + 64) * 4)

__global__ void __launch_bounds__(256) ln_fused(const float* __restrict__ x,
                                                const float* __restrict__ lw,
                                                const float* __restrict__ lb)
{
    extern __shared__ float sm[];
    float* tile = sm;                  // [640][33]
    float* p1 = sm + LN_TILE;          // [8][33]
    float* p2 = p1 + 8 * 33;           // [8][33]
    float* mus = p2 + 8 * 33;          // [32]
    float* rss = mus + 32;             // [32]

    int tid = threadIdx.x, sl = tid & 31, wp = tid >> 5;
    int s0 = blockIdx.x * 32, b = blockIdx.y;

    // load [c][s] tile, coalesced along s
    const float* xb = x + (size_t)b * CHN * SP + s0;
#pragma unroll 8
    for (int it = 0; it < 80; it++) {
        int c = it * 8 + wp;
        tile[c * 33 + sl] = xb[(size_t)c * SP + sl];
    }
    __syncthreads();

    // per-s partial sums over c (8 partials per s)
    float sum = 0.f, sq = 0.f;
#pragma unroll 8
    for (int k = 0; k < 80; k++) {
        float v = tile[(wp + 8 * k) * 33 + sl];
        sum += v; sq += v * v;
    }
    p1[wp * 33 + sl] = sum;
    p2[wp * 33 + sl] = sq;
    __syncthreads();
    if (tid < 32) {
        float S = 0.f, Q = 0.f;
#pragma unroll
        for (int g = 0; g < 8; g++) { S += p1[g * 33 + tid]; Q += p2[g * 33 + tid]; }
        float mu = S * (1.0f / CHN);
        float var = Q * (1.0f / CHN) - mu * mu;
        mus[tid] = mu;
        rss[tid] = rsqrtf(var + 1e-6f);
    }
    __syncthreads();

    // write fp16 [s][c], half2 per thread (coalesced along c)
    __half* ob = g_x16 + ((size_t)b * SP + s0) * CHN;
#pragma unroll 4
    for (int it = 0; it < 40; it++) {
        int idx = it * 256 + tid;          // pair index, 320 pairs per s
        int s = idx / 320, c = (idx - s * 320) * 2;
        float mu = mus[s], rs = rss[s];
        float v0 = (tile[c * 33 + s]       - mu) * rs * lw[c]     + lb[c];
        float v1 = (tile[(c + 1) * 33 + s] - mu) * rs * lw[c + 1] + lb[c + 1];
        *(__half2*)(ob + (size_t)s * CHN + c) = __floats2half2_rn(v0, v1);
    }
}

// ---------------- weight transpose+cvt [R][C] fp32 -> [C][R] fp16 ----------------
__global__ void __launch_bounds__(256) cvt_w_t(const float* __restrict__ in,
                                               __half* __restrict__ out, int R, int C)
{
    __shared__ float t[32][33];
    int c0 = blockIdx.x * 32, r0 = blockIdx.y * 32;
    int xl = threadIdx.x & 31, y = (threadIdx.x >> 5) * 4;
#pragma unroll
    for (int i = 0; i < 4; i++)
        t[y + i][xl] = in[(size_t)(r0 + y + i) * C + c0 + xl];
    __syncthreads();
#pragma unroll
    for (int i = 0; i < 4; i++)
        out[(size_t)(c0 + y + i) * R + r0 + xl] = __float2half_rn(t[xl][y + i]);
}

// ---------------- elementwise cvt ----------------
__global__ void __launch_bounds__(256) cvt16(const float* __restrict__ in,
                                             __half* __restrict__ out, int n)
{
    int i = blockIdx.x * 256 + threadIdx.x;
    if (i < n) out[i] = __float2half_rn(in[i]);
}

// ---------------- fp16 mma GEMM: D = A[M][K] * Bt[N][K]^T ----------------
// EPI 0: C[m][n] fp32;  EPI 1: out[b][n][s] fp32 + bias + resid;  EPI 2: C fp16
#define HBOFF  10240
#define HSTG   20480
#define HGSMEM (3 * HSTG)

template<int EPI, bool MG>
__global__ void __launch_bounds__(256, 2)
gemm_h(const __half* __restrict__ A, const __half* __restrict__ Bt,
       void* __restrict__ CoutV, int M, int N, int K, int lda,
       const float* __restrict__ bias, const float* __restrict__ resid)
{
    extern __shared__ char smc[];
    uint32_t sb = smem_u32(smc);

    int tid = threadIdx.x, lane = tid & 31, w = tid >> 5;
    int r = lane >> 2, q = lane & 3;
    int wm = w & 3, wn = w >> 2;
    int m0 = blockIdx.y * 128;
    int n0 = blockIdx.x * 128;
    int mb = wm * 32, nb = wn * 64;
    int NT = K >> 5;

    uint32_t offA = (uint32_t)((mb + (lane & 15)) * 40 + ((lane & 16) ? 8 : 0)) * 2;
    uint32_t offB = (uint32_t)((nb + (lane & 7) + ((lane & 16) ? 8 : 0)) * 40
                               + ((lane & 8) ? 8 : 0)) * 2;

    float acc[2][8][4];
#pragma unroll
    for (int i = 0; i < 2; i++)
#pragma unroll
        for (int j = 0; j < 8; j++)
#pragma unroll
            for (int l = 0; l < 4; l++) acc[i][j][l] = 0.f;

    auto load_stage = [&](int slot, int k0) {
        uint32_t st = sb + slot * HSTG;
#pragma unroll
        for (int i = 0; i < 2; i++) {
            int cid = tid + i * 256;
            int row = cid >> 2, ch = cid & 3;
            bool v = !MG || (m0 + row) < M;
            cp16(st + row * 80 + ch * 16,
                 A + (size_t)(m0 + row) * lda + k0 + ch * 8, v);
        }
#pragma unroll
        for (int i = 0; i < 2; i++) {
            int cid = tid + i * 256;
            int row = cid >> 2, ch = cid & 3;
            cp16(st + HBOFF + row * 80 + ch * 16,
                 Bt + (size_t)(n0 + row) * K + k0 + ch * 8, true);
        }
    };

    load_stage(0, 0);  CP_COMMIT();
    load_stage(1, 32); CP_COMMIT();

    for (int t = 0; t < NT; t++) {
        if (t == NT - 1) CP_WAIT0(); else CP_WAIT1();
        __syncthreads();
        if (t + 2 < NT) { load_stage((t + 2) % 3, (t + 2) * 32); CP_COMMIT(); }

        int slot = t % 3;
        uint32_t aBase = sb + slot * HSTG + offA;
        uint32_t bBase = sb + slot * HSTG + HBOFF + offB;

        unsigned ac[2][4], an[2][4];
        ldsm4(ac[0], aBase);
        ldsm4(ac[1], aBase + 1280);
#pragma unroll
        for (int kc = 0; kc < 2; kc++) {
            if (kc == 0) {
                ldsm4(an[0], aBase + 32);
                ldsm4(an[1], aBase + 1280 + 32);
            }
            unsigned bb[4][4];
#pragma unroll
            for (int j = 0; j < 4; j++)
                ldsm4(bb[j], bBase + j * 1280 + kc * 32);
#pragma unroll
            for (int j = 0; j < 4; j++) {
#pragma unroll
                for (int im = 0; im < 2; im++)
                    mma_f16(acc[im][2 * j], ac[im][0], ac[im][1], ac[im][2],
                            ac[im][3], bb[j][0], bb[j][1]);
#pragma unroll
                for (int im = 0; im < 2; im++)
                    mma_f16(acc[im][2 * j + 1], ac[im][0], ac[im][1], ac[im][2],
                            ac[im][3], bb[j][2], bb[j][3]);
            }
            if (kc == 0) {
#pragma unroll
                for (int im = 0; im < 2; im++)
#pragma unroll
                    for (int jj = 0; jj < 4; jj++) ac[im][jj] = an[im][jj];
            }
        }
    }
    __syncthreads();

    // -------- epilogue --------
    float* Cs = (float*)smc;
    if (EPI != 1) {
#pragma unroll 1
        for (int ch = 0; ch < 4; ch++) {
            __syncthreads();
            if (wm == ch) {
#pragma unroll
                for (int im = 0; im < 2; im++) {
                    int r0 = im * 16 + r;
#pragma unroll
                    for (int in_ = 0; in_ < 8; in_++) {
                        int cc = nb + in_ * 8 + q * 2;
                        Cs[r0 * 132 + cc]           = acc[im][in_][0];
                        Cs[r0 * 132 + cc + 1]       = acc[im][in_][1];
                        Cs[(r0 + 8) * 132 + cc]     = acc[im][in_][2];
                        Cs[(r0 + 8) * 132 + cc + 1] = acc[im][in_][3];
                    }
                }
            }
            __syncthreads();
            for (int t = tid; t < 32 * 128; t += 256) {
                int ml = t >> 7, n = t & 127;
                int m = m0 + ch * 32 + ml;
                if (MG && m >= M) continue;
                if (EPI == 0)
                    ((float*)CoutV)[(size_t)m * N + n0 + n] = Cs[ml * 132 + n];
                else
                    ((__half*)CoutV)[(size_t)m * N + n0 + n] =
                        __float2half_rn(Cs[ml * 132 + n]);
            }
        }
    } else {
#pragma unroll 1
        for (int ch = 0; ch < 4; ch++) {
            __syncthreads();
            if (wn == (ch >> 1)) {
                int inlo = (ch & 1) * 4;
#pragma unroll
                for (int im = 0; im < 2; im++) {
                    int mrow = mb + im * 16 + r;
#pragma unroll
                    for (int ii = 0; ii < 4; ii++) {
                        int in_ = inlo + ii;
                        int nl = in_ * 8 + q * 2 - (ch & 1) * 32;
                        Cs[nl * 132 + mrow]           = acc[im][in_][0];
                        Cs[(nl + 1) * 132 + mrow]     = acc[im][in_][1];
                        Cs[nl * 132 + mrow + 8]       = acc[im][in_][2];
                        Cs[(nl + 1) * 132 + mrow + 8] = acc[im][in_][3];
                    }
                }
            }
            __syncthreads();
            for (int t = tid; t < 32 * 128; t += 256) {
                int nl = t >> 7, ml = t & 127;
                int n = n0 + ch * 32 + nl;
                int m = m0 + ml;
                int b = m >> 12, s = m & (SP - 1);
                size_t addr = (size_t)b * CHN * SP + (size_t)n * SP + s;
                ((float*)CoutV)[addr] = Cs[nl * 132 + ml] + bias[n] + resid[addr];
            }
        }
    }
}

// ---------------- fp16 tensor-core attention ----------------
#define AT_SMEM 28160

__global__ void __launch_bounds__(256, 2) attn_mma()
{
    extern __shared__ __half smh[];
    __half* Kh = smh;            // [80][88]
    __half* Vh = smh + 7040;     // [80][88]

    int tid = threadIdx.x, lane = tid & 31, w = tid >> 5;
    int b = blockIdx.z, h = blockIdx.y;
    int q0 = blockIdx.x * 128;
    int mb = w * 16;
    int r = lane >> 2, q = lane & 3, q2 = q * 2;
    uint32_t sb = smem_u32(smh);

    const __half* kg = g_kv16 + (size_t)b * TT * KVW + h * HDIM;
    const __half* vg = kg + INNER;

#pragma unroll
    for (int i = 0; i < 4; i++) {
        int cid = tid + i * 256;
        if (cid < 770) {
            int t = cid / 10, ch = cid % 10;
            cp16(sb + (t * 88 + ch * 8) * 2, kg + (size_t)t * KVW + ch * 8, true);
            cp16(sb + (7040 + t * 88 + ch * 8) * 2, vg + (size_t)t * KVW + ch * 8, true);
        }
    }
    CP_COMMIT();

    if (tid < 240) {
        int row = 77 + tid / 80, col = tid % 80;
        Kh[row * 88 + col] = __float2half(0.f);
        Vh[row * 88 + col] = __float2half(0.f);
    }

    const __half* qg = g_q16 + ((size_t)b * SP + q0 + mb) * INNER + h * HDIM;
    unsigned qf[5][4];
#pragma unroll
    for (int k8 = 0; k8 < 5; k8++) {
        int c = k8 * 16 + q2;
        qf[k8][0] = *(const unsigned*)(qg + (size_t)r * INNER + c);
        qf[k8][1] = *(const unsigned*)(qg + (size_t)(r + 8) * INNER + c);
        qf[k8][2] = *(const unsigned*)(qg + (size_t)r * INNER + c + 8);
        qf[k8][3] = *(const unsigned*)(qg + (size_t)(r + 8) * INNER + c + 8);
    }
    CP_WAIT0();
    __syncthreads();

    uint32_t kBase = sb + (uint32_t)(((lane & 7) + ((lane & 16) ? 8 : 0)) * 88
                                     + ((lane & 8) ? 8 : 0)) * 2;
    float acc[10][4];
#pragma unroll
    for (int i = 0; i < 10; i++)
#pragma unroll
        for (int j = 0; j < 4; j++) acc[i][j] = 0.f;

#pragma unroll
    for (int k8 = 0; k8 < 5; k8++) {
#pragma unroll
        for (int tp = 0; tp < 5; tp++) {
            unsigned bb[4];
            ldsm4(bb, kBase + tp * 2816 + k8 * 32);
            mma_f16(acc[2 * tp],     qf[k8][0], qf[k8][1], qf[k8][2], qf[k8][3],
                    bb[0], bb[1]);
            mma_f16(acc[2 * tp + 1], qf[k8][0], qf[k8][1], qf[k8][2], qf[k8][3],
                    bb[2], bb[3]);
        }
    }

    const float scale = 0.11180339887498949f;
    float invs[2];
#pragma unroll
    for (int hf = 0; hf < 2; hf++) {
        float mx = -1e30f;
#pragma unroll
        for (int in_ = 0; in_ < 10; in_++) {
            int c0 = in_ * 8 + q2;
            float v0 = (c0     < TT) ? acc[in_][hf * 2]     * scale : -1e30f;
            float v1 = (c0 + 1 < TT) ? acc[in_][hf * 2 + 1] * scale : -1e30f;
            acc[in_][hf * 2] = v0; acc[in_][hf * 2 + 1] = v1;
            mx = fmaxf(mx, fmaxf(v0, v1));
        }
        mx = fmaxf(mx, __shfl_xor_sync(0xffffffffu, mx, 1));
        mx = fmaxf(mx, __shfl_xor_sync(0xffffffffu, mx, 2));
        float s = 0.f;
#pragma unroll
        for (int in_ = 0; in_ < 10; in_++) {
            int c0 = in_ * 8 + q2;
            float e0 = (c0     < TT) ? __expf(acc[in_][hf * 2]     - mx) : 0.f;
            float e1 = (c0 + 1 < TT) ? __expf(acc[in_][hf * 2 + 1] - mx) : 0.f;
            acc[in_][hf * 2] = e0; acc[in_][hf * 2 + 1] = e1;
            s += e0 + e1;
        }
        s += __shfl_xor_sync(0xffffffffu, s, 1);
        s += __shfl_xor_sync(0xffffffffu, s, 2);
        invs[hf] = 1.f / s;
    }

    unsigned pf[5][4];
#pragma unroll
    for (int k8 = 0; k8 < 5; k8++) {
        __half2 h0 = __floats2half2_rn(acc[2 * k8][0],     acc[2 * k8][1]);
        __half2 h1 = __floats2half2_rn(acc[2 * k8][2],     acc[2 * k8][3]);
        __half2 h2 = __floats2half2_rn(acc[2 * k8 + 1][0], acc[2 * k8 + 1][1]);
        __half2 h3 = __floats2half2_rn(acc[2 * k8 + 1][2], acc[2 * k8 + 1][3]);
        pf[k8][0] = *(unsigned*)&h0;
        pf[k8][1] = *(unsigned*)&h1;
        pf[k8][2] = *(unsigned*)&h2;
        pf[k8][3] = *(unsigned*)&h3;
    }

    uint32_t vBase = sb + 14080 + (uint32_t)(((lane & 7) + ((lane & 16) ? 8 : 0)) * 88) * 2
                   + (uint32_t)((lane & 8) ? 16 : 0);
    float oc[10][4];
#pragma unroll
    for (int i = 0; i < 10; i++)
#pragma unroll
        for (int j = 0; j < 4; j++) oc[i][j] = 0.f;

#pragma unroll
    for (int k8 = 0; k8 < 5; k8++) {
#pragma unroll
        for (int dp = 0; dp < 5; dp++) {
            unsigned vb[4];
            ldsm4t(vb, vBase + k8 * 2816 + dp * 32);
            mma_f16(oc[2 * dp],     pf[k8][0], pf[k8][1], pf[k8][2], pf[k8][3],
                    vb[0], vb[2]);
            mma_f16(oc[2 * dp + 1], pf[k8][0], pf[k8][1], pf[k8][2], pf[k8][3],
                    vb[1], vb[3]);
        }
    }

    __half* og = g_at16 + ((size_t)b * SP + q0 + mb) * INNER + h * HDIM;
#pragma unroll
    for (int in_ = 0; in_ < 10; in_++) {
        int c = in_ * 8 + q2;
        *(__half2*)(og + (size_t)r * INNER + c) =
            __floats2half2_rn(oc[in_][0] * invs[0], oc[in_][1] * invs[0]);
        *(__half2*)(og + (size_t)(r + 8) * INNER + c) =
            __floats2half2_rn(oc[in_][2] * invs[1], oc[in_][3] * invs[1]);
    }
}

// ---------------- launch ----------------
extern "C" void kernel_launch(void* const* d_in, const int* in_sizes, int n_in,
                              void* d_out, int out_size)
{
    (void)in_sizes; (void)n_in; (void)out_size;
    const float* hs  = (const float*)d_in[0];
    const float* enc = (const float*)d_in[1];
    const float* lnw = (const float*)d_in[2];
    const float* lnb = (const float*)d_in[3];
    const float* wq  = (const float*)d_in[4];
    const float* wk  = (const float*)d_in[5];
    const float* wv  = (const float*)d_in[6];
    const float* wo  = (const float*)d_in[7];
    const float* bo  = (const float*)d_in[8];
    float* out = (float*)d_out;

    __half *p_q16, *p_kv16, *p_x16, *p_at16, *p_e16;
    __half *p_wq16, *p_wkv16, *p_wo16;
    cudaGetSymbolAddress((void**)&p_q16,   g_q16);
    cudaGetSymbolAddress((void**)&p_kv16,  g_kv16);
    cudaGetSymbolAddress((void**)&p_x16,   g_x16);
    cudaGetSymbolAddress((void**)&p_at16,  g_at16);
    cudaGetSymbolAddress((void**)&p_e16,   g_e16);
    cudaGetSymbolAddress((void**)&p_wq16,  g_wq16);
    cudaGetSymbolAddress((void**)&p_wkv16, g_wkv16);
    cudaGetSymbolAddress((void**)&p_wo16,  g_wo16);

    static cudaStream_t s1 = nullptr;
    static cudaEvent_t evF = nullptr, evJ = nullptr;
    if (s1 == nullptr) {
        cudaStreamCreateWithFlags(&s1, cudaStreamNonBlocking);
        cudaEventCreateWithFlags(&evF, cudaEventDisableTiming);
        cudaEventCreateWithFlags(&evJ, cudaEventDisableTiming);
        cudaFuncSetAttribute(gemm_h<2, false>,
                             cudaFuncAttributeMaxDynamicSharedMemorySize, HGSMEM);
        cudaFuncSetAttribute(gemm_h<2, true>,
                             cudaFuncAttributeMaxDynamicSharedMemorySize, HGSMEM);
        cudaFuncSetAttribute(gemm_h<1, false>,
                             cudaFuncAttributeMaxDynamicSharedMemorySize, HGSMEM);
        cudaFuncSetAttribute(attn_mma,
                             cudaFuncAttributeMaxDynamicSharedMemorySize, AT_SMEM);
        cudaFuncSetAttribute(ln_fused,
                             cudaFuncAttributeMaxDynamicSharedMemorySize, LN_SMEM);
    }

    // fork: stream B handles wk/wv/wo cvts + enc cvt + fused KV GEMM
    cudaEventRecord(evF, 0);
    cudaStreamWaitEvent(s1, evF, 0);

    cvt_w_t<<<dim3(INNER / 32, XDIM / 32), 256, 0, s1>>>(wk, p_wkv16, XDIM, INNER);
    cvt_w_t<<<dim3(INNER / 32, XDIM / 32), 256, 0, s1>>>(
        wv, p_wkv16 + (size_t)INNER * XDIM, XDIM, INNER);
    cvt_w_t<<<dim3(CHN / 32, INNER / 32), 256, 0, s1>>>(wo, p_wo16, INNER, CHN);
    {
        int n = BATCH * TT * XDIM;
        cvt16<<<(n + 255) / 256, 256, 0, s1>>>(enc, p_e16, n);
    }
    gemm_h<2, true><<<dim3(KVW / 128, (BATCH * TT + 127) / 128), 256, HGSMEM, s1>>>(
        p_e16, p_wkv16, p_kv16, BATCH * TT, KVW, XDIM, XDIM, nullptr, nullptr);
    cudaEventRecord(evJ, s1);

    // --- stream A (default): wq cvt -> fused LN -> Q GEMM ---
    cvt_w_t<<<dim3(INNER / 32, CHN / 32), 256>>>(wq, p_wq16, CHN, INNER);
    ln_fused<<<dim3(SP / 32, BATCH), 256, LN_SMEM>>>(hs, lnw, lnb);
    gemm_h<2, false><<<dim3(INNER / 128, (BATCH * SP) / 128), 256, HGSMEM>>>(
        p_x16, p_wq16, p_q16, BATCH * SP, INNER, CHN, CHN, nullptr, nullptr);

    // join
    cudaStreamWaitEvent(0, evJ, 0);

    // attention (fp16 tensor-core)
    attn_mma<<<dim3(SP / 128, NHE, BATCH), 256, AT_SMEM>>>();

    // out = at16 @ wo16^T + bo + residual (transposed store, fp32)
    gemm_h<1, false><<<dim3(CHN / 128, (BATCH * SP) / 128), 256, HGSMEM>>>(
        p_at16, p_wo16, out, BATCH * SP, CHN, INNER, INNER, bo, hs);
}

// round 16
// speedup vs baseline: 1.1668x; 1.0074x over previous
#include <cuda_runtime.h>
#include <cuda_fp16.h>
#include <math.h>
#include <stdint.h>

#define BATCH 16
#define CHN   640
#define SP    4096
#define TT    77
#define XDIM  768
#define NHE   8
#define HDIM  80
#define INNER 640
#define KVW   1280          // fused K|V width

// ---------------- scratch ----------------
__device__ __half g_q16  [(size_t)BATCH * SP * INNER];
__device__ __half g_kv16 [(size_t)BATCH * TT * KVW];    // [m][ K(640) | V(640) ]
__device__ __half g_x16  [(size_t)BATCH * SP * CHN];
__device__ __half g_at16 [(size_t)BATCH * SP * INNER];
__device__ __half g_e16  [(size_t)BATCH * TT * XDIM];
__device__ __half g_wq16 [(size_t)INNER * CHN];
__device__ __half g_wkv16[(size_t)KVW * XDIM];
__device__ __half g_wo16 [(size_t)CHN * INNER];

// ---------------- helpers ----------------
__device__ __forceinline__ uint32_t smem_u32(const void* p) {
    uint32_t a;
    asm("{ .reg .u64 t; cvta.to.shared.u64 t, %1; cvt.u32.u64 %0, t; }"
        : "=r"(a) : "l"(p));
    return a;
}
__device__ __forceinline__ void cp16(uint32_t dst, const void* src, bool v) {
    int sz = v ? 16 : 0;
    asm volatile("cp.async.cg.shared.global [%0], [%1], 16, %2;"
                 :: "r"(dst), "l"(src), "r"(sz) : "memory");
}
#define CP_COMMIT() asm volatile("cp.async.commit_group;" ::: "memory")
#define CP_WAIT1()  asm volatile("cp.async.wait_group 1;" ::: "memory")
#define CP_WAIT0()  asm volatile("cp.async.wait_group 0;" ::: "memory")

__device__ __forceinline__ void ldsm4(unsigned r[4], uint32_t a) {
    asm volatile("ldmatrix.sync.aligned.m8n8.x4.shared.b16 {%0,%1,%2,%3}, [%4];"
                 : "=r"(r[0]), "=r"(r[1]), "=r"(r[2]), "=r"(r[3]) : "r"(a));
}
__device__ __forceinline__ void ldsm4t(unsigned r[4], uint32_t a) {
    asm volatile("ldmatrix.sync.aligned.m8n8.x4.trans.shared.b16 {%0,%1,%2,%3}, [%4];"
                 : "=r"(r[0]), "=r"(r[1]), "=r"(r[2]), "=r"(r[3]) : "r"(a));
}

__device__ __forceinline__ void mma_f16(float c[4], unsigned a0, unsigned a1,
                                        unsigned a2, unsigned a3,
                                        unsigned b0, unsigned b1)
{
    asm volatile(
        "mma.sync.aligned.m16n8k16.row.col.f32.f16.f16.f32 "
        "{%0,%1,%2,%3},{%4,%5,%6,%7},{%8,%9},{%0,%1,%2,%3};"
        : "+f"(c[0]), "+f"(c[1]), "+f"(c[2]), "+f"(c[3])
        : "r"(a0), "r"(a1), "r"(a2), "r"(a3), "r"(b0), "r"(b1));
}

// ---------------- fused LN: stats + normalize + transpose in one pass ----------------
#define LN_TILE  (CHN * 33)
#define LN_SMEM  ((LN_TILE + 2 * 8 * 33 + 64) * 4)

__global__ void __launch_bounds__(256) ln_fused(const float* __restrict__ x,
                                                const float* __restrict__ lw,
                                                const float* __restrict__ lb)
{
    extern __shared__ float sm[];
    float* tile = sm;                  // [640][33]
    float* p1 = sm + LN_TILE;          // [8][33]
    float* p2 = p1 + 8 * 33;           // [8][33]
    float* mus = p2 + 8 * 33;          // [32]
    float* rss = mus + 32;             // [32]

    int tid = threadIdx.x, sl = tid & 31, wp = tid >> 5;
    int s0 = blockIdx.x * 32, b = blockIdx.y;

    const float* xb = x + (size_t)b * CHN * SP + s0;
#pragma unroll 8
    for (int it = 0; it < 80; it++) {
        int c = it * 8 + wp;
        tile[c * 33 + sl] = xb[(size_t)c * SP + sl];
    }
    __syncthreads();

    float sum = 0.f, sq = 0.f;
#pragma unroll 8
    for (int k = 0; k < 80; k++) {
        float v = tile[(wp + 8 * k) * 33 + sl];
        sum += v; sq += v * v;
    }
    p1[wp * 33 + sl] = sum;
    p2[wp * 33 + sl] = sq;
    __syncthreads();
    if (tid < 32) {
        float S = 0.f, Q = 0.f;
#pragma unroll
        for (int g = 0; g < 8; g++) { S += p1[g * 33 + tid]; Q += p2[g * 33 + tid]; }
        float mu = S * (1.0f / CHN);
        float var = Q * (1.0f / CHN) - mu * mu;
        mus[tid] = mu;
        rss[tid] = rsqrtf(var + 1e-6f);
    }
    __syncthreads();

    __half* ob = g_x16 + ((size_t)b * SP + s0) * CHN;
#pragma unroll 4
    for (int it = 0; it < 40; it++) {
        int idx = it * 256 + tid;
        int s = idx / 320, c = (idx - s * 320) * 2;
        float mu = mus[s], rs = rss[s];
        float v0 = (tile[c * 33 + s]       - mu) * rs * lw[c]     + lb[c];
        float v1 = (tile[(c + 1) * 33 + s] - mu) * rs * lw[c + 1] + lb[c + 1];
        *(__half2*)(ob + (size_t)s * CHN + c) = __floats2half2_rn(v0, v1);
    }
}

// ---------------- weight transpose+cvt ----------------
__global__ void __launch_bounds__(256) cvt_w_t(const float* __restrict__ in,
                                               __half* __restrict__ out, int R, int C)
{
    __shared__ float t[32][33];
    int c0 = blockIdx.x * 32, r0 = blockIdx.y * 32;
    int xl = threadIdx.x & 31, y = (threadIdx.x >> 5) * 4;
#pragma unroll
    for (int i = 0; i < 4; i++)
        t[y + i][xl] = in[(size_t)(r0 + y + i) * C + c0 + xl];
    __syncthreads();
#pragma unroll
    for (int i = 0; i < 4; i++)
        out[(size_t)(c0 + y + i) * R + r0 + xl] = __float2half_rn(t[xl][y + i]);
}

// ---------------- elementwise cvt ----------------
__global__ void __launch_bounds__(256) cvt16(const float* __restrict__ in,
                                             __half* __restrict__ out, int n)
{
    int i = blockIdx.x * 256 + threadIdx.x;
    if (i < n) out[i] = __float2half_rn(in[i]);
}

// ---------------- fp16 mma GEMM: D = A[M][K] * Bt[N][K]^T ----------------
#define HBOFF  10240
#define HSTG   20480
#define HGSMEM (3 * HSTG)

template<int EPI, bool MG>
__global__ void __launch_bounds__(256, 2)
gemm_h(const __half* __restrict__ A, const __half* __restrict__ Bt,
       void* __restrict__ CoutV, int M, int N, int K, int lda,
       const float* __restrict__ bias, const float* __restrict__ resid)
{
    extern __shared__ char smc[];
    uint32_t sb = smem_u32(smc);

    int tid = threadIdx.x, lane = tid & 31, w = tid >> 5;
    int r = lane >> 2, q = lane & 3;
    int wm = w & 3, wn = w >> 2;
    int m0 = blockIdx.y * 128;
    int n0 = blockIdx.x * 128;
    int mb = wm * 32, nb = wn * 64;
    int NT = K >> 5;

    uint32_t offA = (uint32_t)((mb + (lane & 15)) * 40 + ((lane & 16) ? 8 : 0)) * 2;
    uint32_t offB = (uint32_t)((nb + (lane & 7) + ((lane & 16) ? 8 : 0)) * 40
                               + ((lane & 8) ? 8 : 0)) * 2;

    float acc[2][8][4];
#pragma unroll
    for (int i = 0; i < 2; i++)
#pragma unroll
        for (int j = 0; j < 8; j++)
#pragma unroll
            for (int l = 0; l < 4; l++) acc[i][j][l] = 0.f;

    auto load_stage = [&](int slot, int k0) {
        uint32_t st = sb + slot * HSTG;
#pragma unroll
        for (int i = 0; i < 2; i++) {
            int cid = tid + i * 256;
            int row = cid >> 2, ch = cid & 3;
            bool v = !MG || (m0 + row) < M;
            cp16(st + row * 80 + ch * 16,
                 A + (size_t)(m0 + row) * lda + k0 + ch * 8, v);
        }
#pragma unroll
        for (int i = 0; i < 2; i++) {
            int cid = tid + i * 256;
            int row = cid >> 2, ch = cid & 3;
            cp16(st + HBOFF + row * 80 + ch * 16,
                 Bt + (size_t)(n0 + row) * K + k0 + ch * 8, true);
        }
    };

    load_stage(0, 0);  CP_COMMIT();
    load_stage(1, 32); CP_COMMIT();

    for (int t = 0; t < NT; t++) {
        if (t == NT - 1) CP_WAIT0(); else CP_WAIT1();
        __syncthreads();
        if (t + 2 < NT) { load_stage((t + 2) % 3, (t + 2) * 32); CP_COMMIT(); }

        int slot = t % 3;
        uint32_t aBase = sb + slot * HSTG + offA;
        uint32_t bBase = sb + slot * HSTG + HBOFF + offB;

        unsigned ac[2][4], an[2][4];
        ldsm4(ac[0], aBase);
        ldsm4(ac[1], aBase + 1280);
#pragma unroll
        for (int kc = 0; kc < 2; kc++) {
            if (kc == 0) {
                ldsm4(an[0], aBase + 32);
                ldsm4(an[1], aBase + 1280 + 32);
            }
            unsigned bb[4][4];
#pragma unroll
            for (int j = 0; j < 4; j++)
                ldsm4(bb[j], bBase + j * 1280 + kc * 32);
#pragma unroll
            for (int j = 0; j < 4; j++) {
#pragma unroll
                for (int im = 0; im < 2; im++)
                    mma_f16(acc[im][2 * j], ac[im][0], ac[im][1], ac[im][2],
                            ac[im][3], bb[j][0], bb[j][1]);
#pragma unroll
                for (int im = 0; im < 2; im++)
                    mma_f16(acc[im][2 * j + 1], ac[im][0], ac[im][1], ac[im][2],
                            ac[im][3], bb[j][2], bb[j][3]);
            }
            if (kc == 0) {
#pragma unroll
                for (int im = 0; im < 2; im++)
#pragma unroll
                    for (int jj = 0; jj < 4; jj++) ac[im][jj] = an[im][jj];
            }
        }
    }
    __syncthreads();

    // -------- epilogue --------
    float* Cs = (float*)smc;
    if (EPI != 1) {
#pragma unroll 1
        for (int ch = 0; ch < 4; ch++) {
            __syncthreads();
            if (wm == ch) {
#pragma unroll
                for (int im = 0; im < 2; im++) {
                    int r0 = im * 16 + r;
#pragma unroll
                    for (int in_ = 0; in_ < 8; in_++) {
                        int cc = nb + in_ * 8 + q * 2;
                        Cs[r0 * 132 + cc]           = acc[im][in_][0];
                        Cs[r0 * 132 + cc + 1]       = acc[im][in_][1];
                        Cs[(r0 + 8) * 132 + cc]     = acc[im][in_][2];
                        Cs[(r0 + 8) * 132 + cc + 1] = acc[im][in_][3];
                    }
                }
            }
            __syncthreads();
            for (int t = tid; t < 32 * 128; t += 256) {
                int ml = t >> 7, n = t & 127;
                int m = m0 + ch * 32 + ml;
                if (MG && m >= M) continue;
                if (EPI == 0)
                    ((float*)CoutV)[(size_t)m * N + n0 + n] = Cs[ml * 132 + n];
                else
                    ((__half*)CoutV)[(size_t)m * N + n0 + n] =
                        __float2half_rn(Cs[ml * 132 + n]);
            }
        }
    } else {
#pragma unroll 1
        for (int ch = 0; ch < 4; ch++) {
            __syncthreads();
            if (wn == (ch >> 1)) {
                int inlo = (ch & 1) * 4;
#pragma unroll
                for (int im = 0; im < 2; im++) {
                    int mrow = mb + im * 16 + r;
#pragma unroll
                    for (int ii = 0; ii < 4; ii++) {
                        int in_ = inlo + ii;
                        int nl = in_ * 8 + q * 2 - (ch & 1) * 32;
                        Cs[nl * 132 + mrow]           = acc[im][in_][0];
                        Cs[(nl + 1) * 132 + mrow]     = acc[im][in_][1];
                        Cs[nl * 132 + mrow + 8]       = acc[im][in_][2];
                        Cs[(nl + 1) * 132 + mrow + 8] = acc[im][in_][3];
                    }
                }
            }
            __syncthreads();
            for (int t = tid; t < 32 * 128; t += 256) {
                int nl = t >> 7, ml = t & 127;
                int n = n0 + ch * 32 + nl;
                int m = m0 + ml;
                int b = m >> 12, s = m & (SP - 1);
                size_t addr = (size_t)b * CHN * SP + (size_t)n * SP + s;
                ((float*)CoutV)[addr] = Cs[nl * 132 + ml] + bias[n] + resid[addr];
            }
        }
    }
}

// ---------------- fp16 tensor-core attention: 2 q-blocks per CTA ----------------
#define AT_SMEM 28160

__global__ void __launch_bounds__(256, 2) attn_mma()
{
    extern __shared__ __half smh[];
    __half* Kh = smh;            // [80][88]
    __half* Vh = smh + 7040;     // [80][88]

    int tid = threadIdx.x, lane = tid & 31, w = tid >> 5;
    int b = blockIdx.z, h = blockIdx.y;
    int mb = w * 16;
    int r = lane >> 2, q = lane & 3, q2 = q * 2;
    uint32_t sb = smem_u32(smh);

    const __half* kg = g_kv16 + (size_t)b * TT * KVW + h * HDIM;
    const __half* vg = kg + INNER;

    // stage K,V once per CTA
#pragma unroll
    for (int i = 0; i < 4; i++) {
        int cid = tid + i * 256;
        if (cid < 770) {
            int t = cid / 10, ch = cid % 10;
            cp16(sb + (t * 88 + ch * 8) * 2, kg + (size_t)t * KVW + ch * 8, true);
            cp16(sb + (7040 + t * 88 + ch * 8) * 2, vg + (size_t)t * KVW + ch * 8, true);
        }
    }
    CP_COMMIT();

    if (tid < 240) {
        int row = 77 + tid / 80, col = tid % 80;
        Kh[row * 88 + col] = __float2half(0.f);
        Vh[row * 88 + col] = __float2half(0.f);
    }
    CP_WAIT0();
    __syncthreads();

    uint32_t kBase = sb + (uint32_t)(((lane & 7) + ((lane & 16) ? 8 : 0)) * 88
                                     + ((lane & 8) ? 8 : 0)) * 2;
    uint32_t vBase = sb + 14080 + (uint32_t)(((lane & 7) + ((lane & 16) ? 8 : 0)) * 88) * 2
                   + (uint32_t)((lane & 8) ? 16 : 0);
    const float scale = 0.11180339887498949f;

#pragma unroll 1
    for (int qb = 0; qb < 2; qb++) {
        int q0 = blockIdx.x * 256 + qb * 128;

        // Q fragments
        const __half* qg = g_q16 + ((size_t)b * SP + q0 + mb) * INNER + h * HDIM;
        unsigned qf[5][4];
#pragma unroll
        for (int k8 = 0; k8 < 5; k8++) {
            int c = k8 * 16 + q2;
            qf[k8][0] = *(const unsigned*)(qg + (size_t)r * INNER + c);
            qf[k8][1] = *(const unsigned*)(qg + (size_t)(r + 8) * INNER + c);
            qf[k8][2] = *(const unsigned*)(qg + (size_t)r * INNER + c + 8);
            qf[k8][3] = *(const unsigned*)(qg + (size_t)(r + 8) * INNER + c + 8);
        }

        // ---- S = Q K^T ----
        float acc[10][4];
#pragma unroll
        for (int i = 0; i < 10; i++)
#pragma unroll
            for (int j = 0; j < 4; j++) acc[i][j] = 0.f;

#pragma unroll
        for (int k8 = 0; k8 < 5; k8++) {
#pragma unroll
            for (int tp = 0; tp < 5; tp++) {
                unsigned bb[4];
                ldsm4(bb, kBase + tp * 2816 + k8 * 32);
                mma_f16(acc[2 * tp],     qf[k8][0], qf[k8][1], qf[k8][2], qf[k8][3],
                        bb[0], bb[1]);
                mma_f16(acc[2 * tp + 1], qf[k8][0], qf[k8][1], qf[k8][2], qf[k8][3],
                        bb[2], bb[3]);
            }
        }

        // ---- softmax ----
        float invs[2];
#pragma unroll
        for (int hf = 0; hf < 2; hf++) {
            float mx = -1e30f;
#pragma unroll
            for (int in_ = 0; in_ < 10; in_++) {
                int c0 = in_ * 8 + q2;
                float v0 = (c0     < TT) ? acc[in_][hf * 2]     * scale : -1e30f;
                float v1 = (c0 + 1 < TT) ? acc[in_][hf * 2 + 1] * scale : -1e30f;
                acc[in_][hf * 2] = v0; acc[in_][hf * 2 + 1] = v1;
                mx = fmaxf(mx, fmaxf(v0, v1));
            }
            mx = fmaxf(mx, __shfl_xor_sync(0xffffffffu, mx, 1));
            mx = fmaxf(mx, __shfl_xor_sync(0xffffffffu, mx, 2));
            float s = 0.f;
#pragma unroll
            for (int in_ = 0; in_ < 10; in_++) {
                int c0 = in_ * 8 + q2;
                float e0 = (c0     < TT) ? __expf(acc[in_][hf * 2]     - mx) : 0.f;
                float e1 = (c0 + 1 < TT) ? __expf(acc[in_][hf * 2 + 1] - mx) : 0.f;
                acc[in_][hf * 2] = e0; acc[in_][hf * 2 + 1] = e1;
                s += e0 + e1;
            }
            s += __shfl_xor_sync(0xffffffffu, s, 1);
            s += __shfl_xor_sync(0xffffffffu, s, 2);
            invs[hf] = 1.f / s;
        }

        // ---- P fragments ----
        unsigned pf[5][4];
#pragma unroll
        for (int k8 = 0; k8 < 5; k8++) {
            __half2 h0 = __floats2half2_rn(acc[2 * k8][0],     acc[2 * k8][1]);
            __half2 h1 = __floats2half2_rn(acc[2 * k8][2],     acc[2 * k8][3]);
            __half2 h2 = __floats2half2_rn(acc[2 * k8 + 1][0], acc[2 * k8 + 1][1]);
            __half2 h3 = __floats2half2_rn(acc[2 * k8 + 1][2], acc[2 * k8 + 1][3]);
            pf[k8][0] = *(unsigned*)&h0;
            pf[k8][1] = *(unsigned*)&h1;
            pf[k8][2] = *(unsigned*)&h2;
            pf[k8][3] = *(unsigned*)&h3;
        }

        // ---- O = P V ----
        float oc[10][4];
#pragma unroll
        for (int i = 0; i < 10; i++)
#pragma unroll
            for (int j = 0; j < 4; j++) oc[i][j] = 0.f;

#pragma unroll
        for (int k8 = 0; k8 < 5; k8++) {
#pragma unroll
            for (int dp = 0; dp < 5; dp++) {
                unsigned vb[4];
                ldsm4t(vb, vBase + k8 * 2816 + dp * 32);
                mma_f16(oc[2 * dp],     pf[k8][0], pf[k8][1], pf[k8][2], pf[k8][3],
                        vb[0], vb[2]);
                mma_f16(oc[2 * dp + 1], pf[k8][0], pf[k8][1], pf[k8][2], pf[k8][3],
                        vb[1], vb[3]);
            }
        }

        // ---- normalize + write fp16 ----
        __half* og = g_at16 + ((size_t)b * SP + q0 + mb) * INNER + h * HDIM;
#pragma unroll
        for (int in_ = 0; in_ < 10; in_++) {
            int c = in_ * 8 + q2;
            *(__half2*)(og + (size_t)r * INNER + c) =
                __floats2half2_rn(oc[in_][0] * invs[0], oc[in_][1] * invs[0]);
            *(__half2*)(og + (size_t)(r + 8) * INNER + c) =
                __floats2half2_rn(oc[in_][2] * invs[1], oc[in_][3] * invs[1]);
        }
    }
}

// ---------------- launch ----------------
extern "C" void kernel_launch(void* const* d_in, const int* in_sizes, int n_in,
                              void* d_out, int out_size)
{
    (void)in_sizes; (void)n_in; (void)out_size;
    const float* hs  = (const float*)d_in[0];
    const float* enc = (const float*)d_in[1];
    const float* lnw = (const float*)d_in[2];
    const float* lnb = (const float*)d_in[3];
    const float* wq  = (const float*)d_in[4];
    const float* wk  = (const float*)d_in[5];
    const float* wv  = (const float*)d_in[6];
    const float* wo  = (const float*)d_in[7];
    const float* bo  = (const float*)d_in[8];
    float* out = (float*)d_out;

    __half *p_q16, *p_kv16, *p_x16, *p_at16, *p_e16;
    __half *p_wq16, *p_wkv16, *p_wo16;
    cudaGetSymbolAddress((void**)&p_q16,   g_q16);
    cudaGetSymbolAddress((void**)&p_kv16,  g_kv16);
    cudaGetSymbolAddress((void**)&p_x16,   g_x16);
    cudaGetSymbolAddress((void**)&p_at16,  g_at16);
    cudaGetSymbolAddress((void**)&p_e16,   g_e16);
    cudaGetSymbolAddress((void**)&p_wq16,  g_wq16);
    cudaGetSymbolAddress((void**)&p_wkv16, g_wkv16);
    cudaGetSymbolAddress((void**)&p_wo16,  g_wo16);

    static cudaStream_t s1 = nullptr;
    static cudaEvent_t evF = nullptr, evJ = nullptr;
    if (s1 == nullptr) {
        cudaStreamCreateWithFlags(&s1, cudaStreamNonBlocking);
        cudaEventCreateWithFlags(&evF, cudaEventDisableTiming);
        cudaEventCreateWithFlags(&evJ, cudaEventDisableTiming);
        cudaFuncSetAttribute(gemm_h<2, false>,
                             cudaFuncAttributeMaxDynamicSharedMemorySize, HGSMEM);
        cudaFuncSetAttribute(gemm_h<2, true>,
                             cudaFuncAttributeMaxDynamicSharedMemorySize, HGSMEM);
        cudaFuncSetAttribute(gemm_h<1, false>,
                             cudaFuncAttributeMaxDynamicSharedMemorySize, HGSMEM);
        cudaFuncSetAttribute(attn_mma,
                             cudaFuncAttributeMaxDynamicSharedMemorySize, AT_SMEM);
        cudaFuncSetAttribute(ln_fused,
                             cudaFuncAttributeMaxDynamicSharedMemorySize, LN_SMEM);
    }

    // fork: stream B handles wk/wv/wo cvts + enc cvt + fused KV GEMM
    cudaEventRecord(evF, 0);
    cudaStreamWaitEvent(s1, evF, 0);

    cvt_w_t<<<dim3(INNER / 32, XDIM / 32), 256, 0, s1>>>(wk, p_wkv16, XDIM, INNER);
    cvt_w_t<<<dim3(INNER / 32, XDIM / 32), 256, 0, s1>>>(
        wv, p_wkv16 + (size_t)INNER * XDIM, XDIM, INNER);
    cvt_w_t<<<dim3(CHN / 32, INNER / 32), 256, 0, s1>>>(wo, p_wo16, INNER, CHN);
    {
        int n = BATCH * TT * XDIM;
        cvt16<<<(n + 255) / 256, 256, 0, s1>>>(enc, p_e16, n);
    }
    gemm_h<2, true><<<dim3(KVW / 128, (BATCH * TT + 127) / 128), 256, HGSMEM, s1>>>(
        p_e16, p_wkv16, p_kv16, BATCH * TT, KVW, XDIM, XDIM, nullptr, nullptr);
    cudaEventRecord(evJ, s1);

    // --- stream A (default): wq cvt -> fused LN -> Q GEMM ---
    cvt_w_t<<<dim3(INNER / 32, CHN / 32), 256>>>(wq, p_wq16, CHN, INNER);
    ln_fused<<<dim3(SP / 32, BATCH), 256, LN_SMEM>>>(hs, lnw, lnb);
    gemm_h<2, false><<<dim3(INNER / 128, (BATCH * SP) / 128), 256, HGSMEM>>>(
        p_x16, p_wq16, p_q16, BATCH * SP, INNER, CHN, CHN, nullptr, nullptr);

    // join
    cudaStreamWaitEvent(0, evJ, 0);

    // attention (fp16 tensor-core, 2 q-blocks per CTA)
    attn_mma<<<dim3(SP / 256, NHE, BATCH), 256, AT_SMEM>>>();

    // out = at16 @ wo16^T + bo + residual (transposed store, fp32)
    gemm_h<1, false><<<dim3(CHN / 128, (BATCH * SP) / 128), 256, HGSMEM>>>(
        p_at16, p_wo16, out, BATCH * SP, CHN, INNER, INNER, bo, hs);
}